// round 2
// baseline (speedup 1.0000x reference)
#include <cuda_runtime.h>
#include <math.h>

#define HID   128
#define KPF   9                  // k-rows per input feature: 1 silu + 8 spline
#define KTOT  (HID * KPF)        // 1152
#define CH_F  8                  // features per K-chunk
#define CH_K  (CH_F * KPF)       // 72
#define BM    128                // rows per block (layer GEMM)
#define NMAX  131072
#define KPMAX 256

// ---------------- scratch (device globals; no allocation allowed) ----------
__device__ float g_Wc1[KTOT * HID];
__device__ float g_Wc2[KTOT * HID];
__device__ float g_h[(size_t)NMAX * HID];
__device__ float g_pn[KPMAX * HID];

// ---------------- weight prep: Wc[(i*9+slot)*128 + o] ----------------------
__global__ void prep_w_kernel(const float* __restrict__ bw,
                              const float* __restrict__ sw,
                              const float* __restrict__ sc,
                              float* __restrict__ Wc)
{
    int idx = blockIdx.x * 256 + threadIdx.x;   // over (i,o) pairs
    if (idx >= HID * HID) return;
    int i = idx / HID, o = idx % HID;
    Wc[(i * KPF) * HID + o] = bw[o * HID + i];
    float s = sc[o * HID + i];
#pragma unroll
    for (int c = 0; c < 8; ++c)
        Wc[(i * KPF + 1 + c) * HID + o] = sw[(o * HID + i) * 8 + c] * s;
}

// ---------------- prototype normalization ----------------------------------
__global__ void prep_p_kernel(const float* __restrict__ P, float* __restrict__ Pn)
{
    int r = blockIdx.x;
    int t = threadIdx.x;          // 128 threads
    float v = P[r * HID + t];
    float s = v * v;
#pragma unroll
    for (int o = 16; o > 0; o >>= 1) s += __shfl_xor_sync(0xffffffffu, s, o);
    __shared__ float red[4];
    if ((t & 31) == 0) red[t >> 5] = s;
    __syncthreads();
    float tot = red[0] + red[1] + red[2] + red[3];
    float nrm = fmaxf(sqrtf(tot), 1e-8f);
    Pn[r * HID + t] = v / nrm;
}

// ---------------- fused KAN layer: Y = A(X) @ Wc ----------------------------
// A(X) rows: per feature i -> [silu(x_i), B0..B7(x_i)]  (cubic B-splines)
__global__ void __launch_bounds__(256, 1) layer_kernel(
    const float* __restrict__ X, const float* __restrict__ Wc,
    const float* __restrict__ grid, float* __restrict__ Y)
{
    extern __shared__ float sm[];
    float* sX   = sm;                    // BM*HID    = 16384 f
    float* sA   = sX + BM * HID;         // CH_K*BM   = 9216 f   [kk][row]
    float* sW   = sA + CH_K * BM;        // CH_K*HID  = 9216 f   [kk][o]
    float* sg   = sW + CH_K * HID;       // 16 f (12 used)
    float* sinv = sg + 16;               // 32 f (30 used): p=1 @0, p=2 @11, p=3 @21

    const int tid = threadIdx.x;
    const size_t row0 = (size_t)blockIdx.x * BM;

    if (tid < 12) sg[tid] = grid[tid];
    __syncthreads();
    if (tid < 30) {
        int p, j;
        if (tid < 11)      { p = 1; j = tid; }
        else if (tid < 21) { p = 2; j = tid - 11; }
        else               { p = 3; j = tid - 21; }
        sinv[tid] = 1.0f / (sg[j + p] - sg[j]);
    }
    // X tile (coalesced float4)
    {
        const float4* Xv = (const float4*)(X + row0 * HID);
        float4* sXv = (float4*)sX;
#pragma unroll
        for (int it = 0; it < (BM * HID / 4) / 256; ++it)
            sXv[tid + it * 256] = Xv[tid + it * 256];
    }
    __syncthreads();

    float acc[8][8];
#pragma unroll
    for (int r = 0; r < 8; ++r)
#pragma unroll
        for (int c = 0; c < 8; ++c) acc[r][c] = 0.0f;

    const int ty = tid >> 4, tx = tid & 15;

    for (int cc = 0; cc < HID / CH_F; ++cc) {
        // ---- W chunk
        {
            const float4* Wv = (const float4*)(Wc + (size_t)cc * CH_K * HID);
            float4* sWv = (float4*)sW;
#pragma unroll
            for (int it = 0; it < (CH_K * HID / 4) / 256; ++it)
                sWv[tid + it * 256] = Wv[tid + it * 256];
        }
        // ---- A chunk: 8 features x 128 rows, 4 tasks/thread
#pragma unroll
        for (int it = 0; it < (CH_F * BM) / 256; ++it) {
            int t = tid + it * 256;
            int f = t >> 7;            // 0..7
            int r = t & (BM - 1);      // 0..127
            float x = sX[r * HID + cc * CH_F + f];
            float silu = x / (1.0f + __expf(-x));
            float b[11];
#pragma unroll
            for (int j = 0; j < 11; ++j)
                b[j] = (x >= sg[j] && x < sg[j + 1]) ? 1.0f : 0.0f;
#pragma unroll
            for (int p = 1; p <= 3; ++p) {
                const float* inv = sinv + (p == 1 ? 0 : (p == 2 ? 11 : 21));
#pragma unroll
                for (int j = 0; j + p <= 10; ++j)
                    b[j] = (x - sg[j]) * inv[j] * b[j]
                         + (sg[j + p + 1] - x) * inv[j + 1] * b[j + 1];
            }
            float* dst = sA + f * KPF * BM + r;
            dst[0] = silu;
#pragma unroll
            for (int c = 0; c < 8; ++c) dst[(1 + c) * BM] = b[c];
        }
        __syncthreads();
        // ---- 128x128 FMA over 72 k-rows
#pragma unroll 8
        for (int kk = 0; kk < CH_K; ++kk) {
            float4 a0 = *(const float4*)(sA + kk * BM + ty * 8);
            float4 a1 = *(const float4*)(sA + kk * BM + ty * 8 + 4);
            float4 w0 = *(const float4*)(sW + kk * HID + tx * 8);
            float4 w1 = *(const float4*)(sW + kk * HID + tx * 8 + 4);
            float a[8] = {a0.x, a0.y, a0.z, a0.w, a1.x, a1.y, a1.z, a1.w};
            float w[8] = {w0.x, w0.y, w0.z, w0.w, w1.x, w1.y, w1.z, w1.w};
#pragma unroll
            for (int r = 0; r < 8; ++r)
#pragma unroll
                for (int c = 0; c < 8; ++c)
                    acc[r][c] += a[r] * w[c];
        }
        __syncthreads();
    }
#pragma unroll
    for (int r = 0; r < 8; ++r) {
        float* yr = Y + (row0 + ty * 8 + r) * HID + tx * 8;
        *(float4*)(yr)     = make_float4(acc[r][0], acc[r][1], acc[r][2], acc[r][3]);
        *(float4*)(yr + 4) = make_float4(acc[r][4], acc[r][5], acc[r][6], acc[r][7]);
    }
}

// ---------------- argmax of dot(e, pn) (== argmax cosine sim) ---------------
#define AR 64
#define AC 64
__global__ void __launch_bounds__(256, 1) assign_kernel(
    const float* __restrict__ E, const float* __restrict__ Pn,
    int Kp, float* __restrict__ outA)
{
    extern __shared__ float sm[];
    float* sE   = sm;               // AR*HID
    float* sP   = sE + AR * HID;    // AC*HID (xor-swizzled rows)
    float* sVal = sP + AC * HID;    // AR*16
    int*   sIdx = (int*)(sVal + AR * 16);

    const int tid = threadIdx.x;
    const size_t row0 = (size_t)blockIdx.x * AR;
    const int ty = tid >> 4, tx = tid & 15;

    {   // E tile, coalesced, row-major
        const float4* Ev = (const float4*)(E + row0 * HID);
        float4* sEv = (float4*)sE;
#pragma unroll
        for (int it = 0; it < (AR * HID / 4) / 256; ++it)
            sEv[tid + it * 256] = Ev[tid + it * 256];
    }

    float best[4]; int bidx[4];
#pragma unroll
    for (int r = 0; r < 4; ++r) { best[r] = -3.0e38f; bidx[r] = 0; }

    const int sws = (tx & 7) << 2;    // load swizzle: proto p = tx*4+c -> p>>2 == tx

    for (int pc = 0; pc < Kp / AC; ++pc) {
        __syncthreads();
        // proto chunk: lanes vary proto, xor-swizzle k within row
#pragma unroll
        for (int it = 0; it < (AC * HID / 4) / 256; ++it) {
            int t  = tid + it * 256;
            int p  = t & (AC - 1);
            int j4 = t >> 6;           // 0..31
            int k0 = j4 << 2;
            float4 v = *(const float4*)(Pn + (size_t)(pc * AC + p) * HID + k0);
            int sw = ((p >> 2) & 7) << 2;
            *(float4*)(sP + p * HID + (k0 ^ sw)) = v;
        }
        __syncthreads();

        float acc[4][4];
#pragma unroll
        for (int r = 0; r < 4; ++r)
#pragma unroll
            for (int c = 0; c < 4; ++c) acc[r][c] = 0.0f;

#pragma unroll 4
        for (int k = 0; k < HID; k += 4) {
            float4 a[4], pv[4];
#pragma unroll
            for (int r = 0; r < 4; ++r)
                a[r] = *(const float4*)(sE + (ty * 4 + r) * HID + k);
#pragma unroll
            for (int c = 0; c < 4; ++c)
                pv[c] = *(const float4*)(sP + (tx * 4 + c) * HID + (k ^ sws));
#pragma unroll
            for (int r = 0; r < 4; ++r)
#pragma unroll
                for (int c = 0; c < 4; ++c)
                    acc[r][c] += a[r].x * pv[c].x + a[r].y * pv[c].y
                               + a[r].z * pv[c].z + a[r].w * pv[c].w;
        }
#pragma unroll
        for (int c = 0; c < 4; ++c) {
            int idx = pc * AC + tx * 4 + c;
#pragma unroll
            for (int r = 0; r < 4; ++r)
                if (acc[r][c] > best[r]) { best[r] = acc[r][c]; bidx[r] = idx; }
        }
    }
    __syncthreads();
#pragma unroll
    for (int r = 0; r < 4; ++r) {
        sVal[(ty * 4 + r) * 16 + tx] = best[r];
        sIdx[(ty * 4 + r) * 16 + tx] = bidx[r];
    }
    __syncthreads();
    if (tid < AR) {
        float bv = -3.0e38f; int bi = 0x7fffffff;
#pragma unroll
        for (int t = 0; t < 16; ++t) {
            float v = sVal[tid * 16 + t];
            int   i = sIdx[tid * 16 + t];
            if (v > bv || (v == bv && i < bi)) { bv = v; bi = i; }
        }
        outA[row0 + tid] = (float)bi;   // lowest-index tie-break, jnp.argmax semantics
    }
}

// ---------------- launch ----------------------------------------------------
extern "C" void kernel_launch(void* const* d_in, const int* in_sizes, int n_in,
                              void* d_out, int out_size)
{
    const float* x    = (const float*)d_in[0];
    const float* prot = (const float*)d_in[1];
    const float* grid = (const float*)d_in[2];
    const float* bw1  = (const float*)d_in[3];
    const float* sw1  = (const float*)d_in[4];
    const float* sc1  = (const float*)d_in[5];
    const float* bw2  = (const float*)d_in[6];
    const float* sw2  = (const float*)d_in[7];
    const float* sc2  = (const float*)d_in[8];
    float* out = (float*)d_out;

    const int N  = in_sizes[0] / HID;   // 131072
    const int Kp = in_sizes[1] / HID;   // 256

    float *Wc1, *Wc2, *h, *pn;
    cudaGetSymbolAddress((void**)&Wc1, g_Wc1);
    cudaGetSymbolAddress((void**)&Wc2, g_Wc2);
    cudaGetSymbolAddress((void**)&h,   g_h);
    cudaGetSymbolAddress((void**)&pn,  g_pn);

    const int SMEM_LAYER  = (BM * HID + CH_K * BM + CH_K * HID + 48) * 4;     // ~139.5 KB
    const int SMEM_ASSIGN = (AR * HID + AC * HID + AR * 16 + AR * 16) * 4;    // 72 KB
    cudaFuncSetAttribute(layer_kernel,  cudaFuncAttributeMaxDynamicSharedMemorySize, SMEM_LAYER);
    cudaFuncSetAttribute(assign_kernel, cudaFuncAttributeMaxDynamicSharedMemorySize, SMEM_ASSIGN);

    prep_w_kernel<<<(HID * HID + 255) / 256, 256>>>(bw1, sw1, sc1, Wc1);
    prep_w_kernel<<<(HID * HID + 255) / 256, 256>>>(bw2, sw2, sc2, Wc2);
    prep_p_kernel<<<Kp, HID>>>(prot, pn);

    layer_kernel<<<N / BM, 256, SMEM_LAYER>>>(x, Wc1, grid, h);
    layer_kernel<<<N / BM, 256, SMEM_LAYER>>>(h, Wc2, grid, out);

    if ((size_t)out_size >= (size_t)N * HID + (size_t)N)
        assign_kernel<<<N / AR, 256, SMEM_ASSIGN>>>(out, pn, Kp, out + (size_t)N * HID);
}

// round 7
// speedup vs baseline: 1.2651x; 1.2651x over previous
#include <cuda_runtime.h>
#include <cuda_bf16.h>
#include <math.h>
#include <cstdint>

#define HID   128
#define NCH   18                 // 2 silu chunks + 16 spline chunks, 64 k each
#define BM    128
#define NMAX  131072
#define KPMAX 256

#define ASTR  144                // A row stride bytes (64 k * 2B + 16B pad)
#define ATILE 18432              // 128 * 144 (one image: hi|mid|lo)
#define WSTR  272                // W k-row stride bytes (128 o * 2B + 16B pad)
#define WIMG  17408              // 64 * 272 (one image)
#define WBLOB (3 * WIMG)         // 52224: hi | mid | lo
#define AOFF  66048              // after sX [128][129] floats
#define WOFF  (AOFF + 3 * ATILE) // 121344; two W buffers follow
#define SMEM_LAYER (WOFF + 2 * WBLOB)   // 225792 (< 227KB opt-in)

// ---------------- scratch (device globals; no allocation allowed) ----------
__device__ uint4 g_W1[(NCH * WBLOB) / 16];
__device__ uint4 g_W2[(NCH * WBLOB) / 16];
__device__ float g_h[(size_t)NMAX * HID];
__device__ float g_pn[KPMAX * HID];

// ---------------- PTX helpers (sm_80-portable; no tcgen05) ------------------
__device__ __forceinline__ uint32_t smem_u32(const void* p) {
    uint32_t a;
    asm("{ .reg .u64 t; cvta.to.shared.u64 t, %1; cvt.u32.u64 %0, t; }" : "=r"(a) : "l"(p));
    return a;
}
__device__ __forceinline__ void ldm_x4(uint32_t* r, uint32_t a) {
    asm volatile("ldmatrix.sync.aligned.m8n8.x4.shared.b16 {%0,%1,%2,%3}, [%4];"
        : "=r"(r[0]), "=r"(r[1]), "=r"(r[2]), "=r"(r[3]) : "r"(a));
}
__device__ __forceinline__ void ldm_x4t(uint32_t* r, uint32_t a) {
    asm volatile("ldmatrix.sync.aligned.m8n8.x4.trans.shared.b16 {%0,%1,%2,%3}, [%4];"
        : "=r"(r[0]), "=r"(r[1]), "=r"(r[2]), "=r"(r[3]) : "r"(a));
}
__device__ __forceinline__ void mma16816(float* d, const uint32_t* a, const uint32_t* b) {
    asm volatile("mma.sync.aligned.m16n8k16.row.col.f32.bf16.bf16.f32 "
        "{%0,%1,%2,%3}, {%4,%5,%6,%7}, {%8,%9}, {%0,%1,%2,%3};"
        : "+f"(d[0]), "+f"(d[1]), "+f"(d[2]), "+f"(d[3])
        : "r"(a[0]), "r"(a[1]), "r"(a[2]), "r"(a[3]), "r"(b[0]), "r"(b[1]));
}
__device__ __forceinline__ void cp16(uint32_t saddr, const void* gaddr) {
    asm volatile("cp.async.cg.shared.global [%0], [%1], 16;" :: "r"(saddr), "l"(gaddr));
}

// ---------------- 3-way bf16 split ------------------------------------------
__device__ __forceinline__ void split3(float a, __nv_bfloat16& h, __nv_bfloat16& m,
                                       __nv_bfloat16& l) {
    h = __float2bfloat16(a);
    float r1 = a - __bfloat162float(h);
    m = __float2bfloat16(r1);
    l = __float2bfloat16(r1 - __bfloat162float(m));
}

// ---------------- weight prep: k-major bf16 hi/mid/lo images ----------------
// chunk<2: base path, k = feature. chunk>=2: spline, k = f_local*8 + coef.
__global__ void prep_w_kernel(const float* __restrict__ bw,
                              const float* __restrict__ sw,
                              const float* __restrict__ sc,
                              char* __restrict__ Wout)
{
    int idx = blockIdx.x * 256 + threadIdx.x;      // (chunk, k, o)
    if (idx >= NCH * 64 * HID) return;
    int chunk = idx / (64 * HID);
    int rem   = idx - chunk * (64 * HID);
    int k = rem >> 7, o = rem & 127;
    float w;
    if (chunk < 2) {
        w = bw[o * HID + chunk * 64 + k];
    } else {
        int f = (chunk - 2) * 8 + (k >> 3);
        w = sw[(o * HID + f) * 8 + (k & 7)] * sc[o * HID + f];
    }
    __nv_bfloat16 h, m, l;
    split3(w, h, m, l);
    char* base = Wout + (size_t)chunk * WBLOB + k * WSTR + o * 2;
    *(__nv_bfloat16*)(base)            = h;
    *(__nv_bfloat16*)(base + WIMG)     = m;
    *(__nv_bfloat16*)(base + 2 * WIMG) = l;
}

// ---------------- prototype normalization ----------------------------------
__global__ void prep_p_kernel(const float* __restrict__ P, float* __restrict__ Pn)
{
    int r = blockIdx.x, t = threadIdx.x;
    float v = P[r * HID + t];
    float s = v * v;
#pragma unroll
    for (int o = 16; o > 0; o >>= 1) s += __shfl_xor_sync(0xffffffffu, s, o);
    __shared__ float red[4];
    if ((t & 31) == 0) red[t >> 5] = s;
    __syncthreads();
    float nrm = fmaxf(sqrtf(red[0] + red[1] + red[2] + red[3]), 1e-8f);
    Pn[r * HID + t] = v / nrm;
}

// ---------------- A pack: 8 values -> bf16 hi/mid/lo, 16B stores ------------
__device__ __forceinline__ void store8(char* Ab, int r, int blk, const float* v)
{
    __nv_bfloat16 h[8], m[8], l[8];
#pragma unroll
    for (int e = 0; e < 8; ++e) split3(v[e], h[e], m[e], l[e]);
    uint32_t off = r * ASTR + blk * 16;
    *(uint4*)(Ab + off)             = *(uint4*)h;
    *(uint4*)(Ab + ATILE + off)     = *(uint4*)m;
    *(uint4*)(Ab + 2 * ATILE + off) = *(uint4*)l;
}

// ---------------- fused KAN layer on HMMA (bf16x3, two-stage accum) ---------
// CTA: 128 rows x 128 outs. 8 warps: wm=wid>>1 (32 rows), wn=wid&1 (64 cols).
// Per chunk: zeroed acc_work takes 24 RZ-chained MMAs; flushed into acc_total
// with RN CUDA-core adds. Kills the tensor-core RZ accumulation bias.
__global__ void __launch_bounds__(256, 1) layer_mma_kernel(
    const float* __restrict__ X, const char* __restrict__ Wg,
    const float* __restrict__ grid, float* __restrict__ Y)
{
    extern __shared__ char smem[];
    float* sX = (float*)smem;                       // [128][129]
    char*  Ab = smem + AOFF;                        // Ahi | Amid | Alo
    const uint32_t sbase = smem_u32(smem);
    const uint32_t Abase = sbase + AOFF;
    const uint32_t Wbase = sbase + WOFF;

    const int tid = threadIdx.x;
    const int wid = tid >> 5, lane = tid & 31;
    const int wm = wid >> 1, wn = wid & 1;
    const size_t row0 = (size_t)blockIdx.x * BM;

    // X tile, coalesced, padded rows
#pragma unroll 4
    for (int it = 0; it < 64; ++it) {
        int idx = tid + it * 256;
        int r = idx >> 7, c = idx & 127;
        sX[r * 129 + c] = X[(row0 + r) * HID + c];
    }
    const float g0   = grid[0];
    const float invh = 1.0f / (grid[1] - grid[0]);

    // prefetch W chunk 0 into buffer 0
    for (int i = tid; i < WBLOB / 16; i += 256)
        cp16(Wbase + i * 16, Wg + i * 16);
    asm volatile("cp.async.commit_group;");
    __syncthreads();

    float accT[2][8][4];                            // running total (RN adds)
#pragma unroll
    for (int mt = 0; mt < 2; ++mt)
#pragma unroll
        for (int nt = 0; nt < 8; ++nt)
#pragma unroll
            for (int e = 0; e < 4; ++e) accT[mt][nt][e] = 0.0f;

    // per-thread ldmatrix base addresses
    const uint32_t aAddr = Abase + (wm * 32 + (lane & 15)) * ASTR + (lane >> 4) * 16;
    const uint32_t wCol  = wn * 128 + (lane >> 4) * 16;        // bytes into k-row
    const uint32_t wRow  = (uint32_t)(lane & 15) * WSTR;

    for (int c = 0; c < NCH; ++c) {
        // ---- generate A chunk (hi/mid/lo bf16) ----
        if (c < 2) {
#pragma unroll
            for (int it = 0; it < 4; ++it) {
                int t = tid + it * 256;
                int r = t & 127, blk = t >> 7;
                const float* xr = sX + r * 129 + c * 64 + blk * 8;
                float v[8];
#pragma unroll
                for (int e = 0; e < 8; ++e) {
                    float x = xr[e];
                    v[e] = x / (1.0f + __expf(-x));
                }
                store8(Ab, r, blk, v);
            }
        } else {
            const int f0 = (c - 2) * 8;
#pragma unroll
            for (int it = 0; it < 4; ++it) {
                int t = tid + it * 256;
                int r = t & 127, fl = t >> 7;
                float x = sX[r * 129 + f0 + fl];
                float tt = (x - g0) * invh;              // uniform-grid cubic B-spline
                float fi = floorf(tt);
                int   i  = (int)fi;
                float u  = tt - fi;
                float u2 = u * u, u3 = u2 * u, om = 1.0f - u;
                float c0v = u3 * (1.0f / 6.0f);
                float c1v = (1.0f / 6.0f) * (1.0f + 3.0f * u + 3.0f * u2 - 3.0f * u3);
                float c2v = (1.0f / 6.0f) * (4.0f - 6.0f * u2 + 3.0f * u3);
                float c3v = om * om * om * (1.0f / 6.0f);
                float v[8];
#pragma unroll
                for (int j = 0; j < 8; ++j) {
                    int mm_ = i - j;
                    float val = 0.0f;
                    val = (mm_ == 0) ? c0v : val;
                    val = (mm_ == 1) ? c1v : val;
                    val = (mm_ == 2) ? c2v : val;
                    val = (mm_ == 3) ? c3v : val;
                    v[j] = val;
                }
                store8(Ab, r, fl, v);
            }
        }

        // ---- prefetch W(c+1), wait W(c) ----
        if (c + 1 < NCH) {
            const char* src = Wg + (size_t)(c + 1) * WBLOB;
            uint32_t dst = Wbase + ((c + 1) & 1) * WBLOB;
            for (int i = tid; i < WBLOB / 16; i += 256)
                cp16(dst + i * 16, src + i * 16);
            asm volatile("cp.async.commit_group;");
            asm volatile("cp.async.wait_group 1;");
        } else {
            asm volatile("cp.async.wait_group 0;");
        }
        __syncthreads();

        // ---- MMA phase: zeroed chunk accumulator, 4 k16-steps, 6 products ----
        float accW[2][8][4];
#pragma unroll
        for (int mt = 0; mt < 2; ++mt)
#pragma unroll
            for (int nt = 0; nt < 8; ++nt)
#pragma unroll
                for (int e = 0; e < 4; ++e) accW[mt][nt][e] = 0.0f;

        const uint32_t Wb = Wbase + (c & 1) * WBLOB;
#pragma unroll
        for (int ks = 0; ks < 4; ++ks) {
            uint32_t ah[2][4], am[2][4], al[2][4];
#pragma unroll
            for (int mt = 0; mt < 2; ++mt) {
                uint32_t a = aAddr + mt * (16 * ASTR) + ks * 32;
                ldm_x4(ah[mt], a);
                ldm_x4(am[mt], a + ATILE);
                ldm_x4(al[mt], a + 2 * ATILE);
            }
#pragma unroll
            for (int g = 0; g < 4; ++g) {
                uint32_t wh[4], wmr[4], wl[4];
                uint32_t a = Wb + wRow + ks * (16 * WSTR) + wCol + g * 32;
                ldm_x4t(wh,  a);
                ldm_x4t(wmr, a + WIMG);
                ldm_x4t(wl,  a + 2 * WIMG);
#pragma unroll
                for (int mt = 0; mt < 2; ++mt) {
                    float* a0 = accW[mt][2 * g];
                    float* a1 = accW[mt][2 * g + 1];
                    mma16816(a0, ah[mt], wh);       mma16816(a1, ah[mt], wh + 2);
                    mma16816(a0, ah[mt], wmr);      mma16816(a1, ah[mt], wmr + 2);
                    mma16816(a0, am[mt], wh);       mma16816(a1, am[mt], wh + 2);
                    mma16816(a0, am[mt], wmr);      mma16816(a1, am[mt], wmr + 2);
                    mma16816(a0, ah[mt], wl);       mma16816(a1, ah[mt], wl + 2);
                    mma16816(a0, al[mt], wh);       mma16816(a1, al[mt], wh + 2);
                }
            }
        }
        // ---- flush chunk into total (RN adds on CUDA cores) ----
#pragma unroll
        for (int mt = 0; mt < 2; ++mt)
#pragma unroll
            for (int nt = 0; nt < 8; ++nt)
#pragma unroll
                for (int e = 0; e < 4; ++e) accT[mt][nt][e] += accW[mt][nt][e];

        __syncthreads();           // A buffer reused next chunk
    }

    // ---- epilogue: fragment -> gmem ----
#pragma unroll
    for (int mt = 0; mt < 2; ++mt) {
        size_t row = row0 + wm * 32 + mt * 16 + (lane >> 2);
#pragma unroll
        for (int nt = 0; nt < 8; ++nt) {
            int col = wn * 64 + nt * 8 + (lane & 3) * 2;
            *(float2*)&Y[row * HID + col]       = make_float2(accT[mt][nt][0], accT[mt][nt][1]);
            *(float2*)&Y[(row + 8) * HID + col] = make_float2(accT[mt][nt][2], accT[mt][nt][3]);
        }
    }
}

// ---------------- argmax of dot(e, pn) (== argmax cosine sim) ---------------
#define AR 64
#define AC 64
__global__ void __launch_bounds__(256, 1) assign_kernel(
    const float* __restrict__ E, const float* __restrict__ Pn,
    int Kp, float* __restrict__ outA)
{
    extern __shared__ float sm[];
    float* sE   = sm;
    float* sP   = sE + AR * HID;
    float* sVal = sP + AC * HID;
    int*   sIdx = (int*)(sVal + AR * 16);

    const int tid = threadIdx.x;
    const size_t row0 = (size_t)blockIdx.x * AR;
    const int ty = tid >> 4, tx = tid & 15;

    {
        const float4* Ev = (const float4*)(E + row0 * HID);
        float4* sEv = (float4*)sE;
#pragma unroll
        for (int it = 0; it < (AR * HID / 4) / 256; ++it)
            sEv[tid + it * 256] = Ev[tid + it * 256];
    }

    float best[4]; int bidx[4];
#pragma unroll
    for (int r = 0; r < 4; ++r) { best[r] = -3.0e38f; bidx[r] = 0; }

    const int sws = (tx & 7) << 2;

    for (int pc = 0; pc < Kp / AC; ++pc) {
        __syncthreads();
#pragma unroll
        for (int it = 0; it < (AC * HID / 4) / 256; ++it) {
            int t  = tid + it * 256;
            int p  = t & (AC - 1);
            int k0 = (t >> 6) << 2;
            float4 v = *(const float4*)(Pn + (size_t)(pc * AC + p) * HID + k0);
            int sw = ((p >> 2) & 7) << 2;
            *(float4*)(sP + p * HID + (k0 ^ sw)) = v;
        }
        __syncthreads();

        float acc[4][4];
#pragma unroll
        for (int r = 0; r < 4; ++r)
#pragma unroll
            for (int c = 0; c < 4; ++c) acc[r][c] = 0.0f;

#pragma unroll 4
        for (int k = 0; k < HID; k += 4) {
            float4 a[4], pv[4];
#pragma unroll
            for (int r = 0; r < 4; ++r)
                a[r] = *(const float4*)(sE + (ty * 4 + r) * HID + k);
#pragma unroll
            for (int c = 0; c < 4; ++c)
                pv[c] = *(const float4*)(sP + (tx * 4 + c) * HID + (k ^ sws));
#pragma unroll
            for (int r = 0; r < 4; ++r)
#pragma unroll
                for (int c = 0; c < 4; ++c)
                    acc[r][c] += a[r].x * pv[c].x + a[r].y * pv[c].y
                               + a[r].z * pv[c].z + a[r].w * pv[c].w;
        }
#pragma unroll
        for (int c = 0; c < 4; ++c) {
            int idx = pc * AC + tx * 4 + c;
#pragma unroll
            for (int r = 0; r < 4; ++r)
                if (acc[r][c] > best[r]) { best[r] = acc[r][c]; bidx[r] = idx; }
        }
    }
    __syncthreads();
#pragma unroll
    for (int r = 0; r < 4; ++r) {
        sVal[(ty * 4 + r) * 16 + tx] = best[r];
        sIdx[(ty * 4 + r) * 16 + tx] = bidx[r];
    }
    __syncthreads();
    if (tid < AR) {
        float bv = -3.0e38f; int bi = 0x7fffffff;
#pragma unroll
        for (int t = 0; t < 16; ++t) {
            float v = sVal[tid * 16 + t];
            int   i = sIdx[tid * 16 + t];
            if (v > bv || (v == bv && i < bi)) { bv = v; bi = i; }
        }
        outA[row0 + tid] = (float)bi;
    }
}

// ---------------- launch ----------------------------------------------------
extern "C" void kernel_launch(void* const* d_in, const int* in_sizes, int n_in,
                              void* d_out, int out_size)
{
    const float* x    = (const float*)d_in[0];
    const float* prot = (const float*)d_in[1];
    const float* grid = (const float*)d_in[2];
    const float* bw1  = (const float*)d_in[3];
    const float* sw1  = (const float*)d_in[4];
    const float* sc1  = (const float*)d_in[5];
    const float* bw2  = (const float*)d_in[6];
    const float* sw2  = (const float*)d_in[7];
    const float* sc2  = (const float*)d_in[8];
    float* out = (float*)d_out;

    const int N  = in_sizes[0] / HID;
    const int Kp = in_sizes[1] / HID;

    uint4 *W1, *W2; float *h, *pn;
    cudaGetSymbolAddress((void**)&W1, g_W1);
    cudaGetSymbolAddress((void**)&W2, g_W2);
    cudaGetSymbolAddress((void**)&h,  g_h);
    cudaGetSymbolAddress((void**)&pn, g_pn);

    const int SMEM_ASSIGN = (AR * HID + AC * HID + AR * 16 + AR * 16) * 4;    // 72 KB
    cudaFuncSetAttribute(layer_mma_kernel, cudaFuncAttributeMaxDynamicSharedMemorySize, SMEM_LAYER);
    cudaFuncSetAttribute(assign_kernel,    cudaFuncAttributeMaxDynamicSharedMemorySize, SMEM_ASSIGN);

    const int wtasks = NCH * 64 * HID;
    prep_w_kernel<<<(wtasks + 255) / 256, 256>>>(bw1, sw1, sc1, (char*)W1);
    prep_w_kernel<<<(wtasks + 255) / 256, 256>>>(bw2, sw2, sc2, (char*)W2);
    prep_p_kernel<<<Kp, HID>>>(prot, pn);

    layer_mma_kernel<<<N / BM, 256, SMEM_LAYER>>>(x, (const char*)W1, grid, h);
    layer_mma_kernel<<<N / BM, 256, SMEM_LAYER>>>(h, (const char*)W2, grid, out);

    if ((size_t)out_size >= (size_t)N * HID + (size_t)N)
        assign_kernel<<<N / AR, 256, SMEM_ASSIGN>>>(out, pn, Kp, out + (size_t)N * HID);
}

// round 8
// speedup vs baseline: 1.3725x; 1.0849x over previous
#include <cuda_runtime.h>
#include <cuda_bf16.h>
#include <math.h>
#include <cstdint>

#define HID   128
#define NCH   18                 // 2 silu chunks + 16 spline chunks, 64 k each
#define BM    128
#define NMAX  131072
#define KPMAX 256

#define ASTR  144                // A row stride bytes (64 k * 2B + 16B pad)
#define ATILE 18432              // 128 * 144 (one image)
#define ABUF  (3 * ATILE)        // 55296: hi | mid | lo
#define WSTR  272                // W k-row stride bytes (128 o * 2B + 16B pad)
#define WIMG  17408              // 64 * 272 (one image)
#define WBLOB (3 * WIMG)         // 52224: hi | mid | lo
#define WOFF  (2 * ABUF)         // 110592
#define SMEM_LAYER (WOFF + 2 * WBLOB)   // 215040 (< 227KB opt-in)

// ---------------- scratch (device globals; no allocation allowed) ----------
__device__ uint4 g_W1[(NCH * WBLOB) / 16];
__device__ uint4 g_W2[(NCH * WBLOB) / 16];
__device__ float g_h[(size_t)NMAX * HID];
__device__ float g_pn[KPMAX * HID];

// ---------------- PTX helpers (sm_80-portable; no tcgen05) ------------------
__device__ __forceinline__ uint32_t smem_u32(const void* p) {
    uint32_t a;
    asm("{ .reg .u64 t; cvta.to.shared.u64 t, %1; cvt.u32.u64 %0, t; }" : "=r"(a) : "l"(p));
    return a;
}
__device__ __forceinline__ void ldm_x4(uint32_t* r, uint32_t a) {
    asm volatile("ldmatrix.sync.aligned.m8n8.x4.shared.b16 {%0,%1,%2,%3}, [%4];"
        : "=r"(r[0]), "=r"(r[1]), "=r"(r[2]), "=r"(r[3]) : "r"(a));
}
__device__ __forceinline__ void ldm_x4t(uint32_t* r, uint32_t a) {
    asm volatile("ldmatrix.sync.aligned.m8n8.x4.trans.shared.b16 {%0,%1,%2,%3}, [%4];"
        : "=r"(r[0]), "=r"(r[1]), "=r"(r[2]), "=r"(r[3]) : "r"(a));
}
__device__ __forceinline__ void mma16816(float* d, const uint32_t* a, const uint32_t* b) {
    asm volatile("mma.sync.aligned.m16n8k16.row.col.f32.bf16.bf16.f32 "
        "{%0,%1,%2,%3}, {%4,%5,%6,%7}, {%8,%9}, {%0,%1,%2,%3};"
        : "+f"(d[0]), "+f"(d[1]), "+f"(d[2]), "+f"(d[3])
        : "r"(a[0]), "r"(a[1]), "r"(a[2]), "r"(a[3]), "r"(b[0]), "r"(b[1]));
}
__device__ __forceinline__ void cp16(uint32_t saddr, const void* gaddr) {
    asm volatile("cp.async.cg.shared.global [%0], [%1], 16;" :: "r"(saddr), "l"(gaddr));
}

// ---------------- 3-way bf16 split ------------------------------------------
__device__ __forceinline__ void split3(float a, __nv_bfloat16& h, __nv_bfloat16& m,
                                       __nv_bfloat16& l) {
    h = __float2bfloat16(a);
    float r1 = a - __bfloat162float(h);
    m = __float2bfloat16(r1);
    l = __float2bfloat16(r1 - __bfloat162float(m));
}

// ---------------- weight prep: k-major bf16 hi/mid/lo images ----------------
__global__ void prep_w_kernel(const float* __restrict__ bw,
                              const float* __restrict__ sw,
                              const float* __restrict__ sc,
                              char* __restrict__ Wout)
{
    int idx = blockIdx.x * 256 + threadIdx.x;      // (chunk, k, o)
    if (idx >= NCH * 64 * HID) return;
    int chunk = idx / (64 * HID);
    int rem   = idx - chunk * (64 * HID);
    int k = rem >> 7, o = rem & 127;
    float w;
    if (chunk < 2) {
        w = bw[o * HID + chunk * 64 + k];
    } else {
        int f = (chunk - 2) * 8 + (k >> 3);
        w = sw[(o * HID + f) * 8 + (k & 7)] * sc[o * HID + f];
    }
    __nv_bfloat16 h, m, l;
    split3(w, h, m, l);
    char* base = Wout + (size_t)chunk * WBLOB + k * WSTR + o * 2;
    *(__nv_bfloat16*)(base)            = h;
    *(__nv_bfloat16*)(base + WIMG)     = m;
    *(__nv_bfloat16*)(base + 2 * WIMG) = l;
}

// ---------------- prototype normalization ----------------------------------
__global__ void prep_p_kernel(const float* __restrict__ P, float* __restrict__ Pn)
{
    int r = blockIdx.x, t = threadIdx.x;
    float v = P[r * HID + t];
    float s = v * v;
#pragma unroll
    for (int o = 16; o > 0; o >>= 1) s += __shfl_xor_sync(0xffffffffu, s, o);
    __shared__ float red[4];
    if ((t & 31) == 0) red[t >> 5] = s;
    __syncthreads();
    float nrm = fmaxf(sqrtf(red[0] + red[1] + red[2] + red[3]), 1e-8f);
    Pn[r * HID + t] = v / nrm;
}

// ---------------- A pack: 8 values -> bf16 hi/mid/lo, 16B stores ------------
__device__ __forceinline__ void store8(char* Ab, int r, int blk, const float* v)
{
    __nv_bfloat16 h[8], m[8], l[8];
#pragma unroll
    for (int e = 0; e < 8; ++e) split3(v[e], h[e], m[e], l[e]);
    uint32_t off = r * ASTR + blk * 16;
    *(uint4*)(Ab + off)             = *(uint4*)h;
    *(uint4*)(Ab + ATILE + off)     = *(uint4*)m;
    *(uint4*)(Ab + 2 * ATILE + off) = *(uint4*)l;
}

// ---------------- A-chunk generation (reads x from gmem/L2) -----------------
__device__ __forceinline__ void gen_chunk(int cc, char* Ab, const float* __restrict__ X,
                                          size_t row0, int tid, float g0, float invh)
{
    if (cc < 2) {
#pragma unroll
        for (int it = 0; it < 4; ++it) {
            int t = tid + it * 256;
            int r = t >> 3, blk = t & 7;
            const float4* xp = (const float4*)(X + (row0 + r) * HID + cc * 64 + blk * 8);
            float4 x0 = xp[0], x1 = xp[1];
            float v[8] = {x0.x, x0.y, x0.z, x0.w, x1.x, x1.y, x1.z, x1.w};
#pragma unroll
            for (int e = 0; e < 8; ++e) {
                float x = v[e];
                v[e] = x / (1.0f + __expf(-x));
            }
            store8(Ab, r, blk, v);
        }
    } else {
        const int f0 = (cc - 2) * 8;
#pragma unroll
        for (int it = 0; it < 4; ++it) {
            int t = tid + it * 256;
            int r = t >> 3, fl = t & 7;
            float x = X[(row0 + r) * HID + f0 + fl];
            float tt = (x - g0) * invh;              // uniform-grid cubic B-spline
            float fi = floorf(tt);
            int   i  = (int)fi;
            float u  = tt - fi;
            float u2 = u * u, u3 = u2 * u, om = 1.0f - u;
            float c0v = u3 * (1.0f / 6.0f);
            float c1v = (1.0f / 6.0f) * (1.0f + 3.0f * u + 3.0f * u2 - 3.0f * u3);
            float c2v = (1.0f / 6.0f) * (4.0f - 6.0f * u2 + 3.0f * u3);
            float c3v = om * om * om * (1.0f / 6.0f);
            float v[8];
#pragma unroll
            for (int j = 0; j < 8; ++j) {
                int mm_ = i - j;
                float val = 0.0f;
                val = (mm_ == 0) ? c0v : val;
                val = (mm_ == 1) ? c1v : val;
                val = (mm_ == 2) ? c2v : val;
                val = (mm_ == 3) ? c3v : val;
                v[j] = val;
            }
            store8(Ab, r, fl, v);
        }
    }
}

// ---------------- fused KAN layer on HMMA (bf16x3, overlapped gen) ----------
// CTA: 128 rows x 128 outs. 8 warps: wm=wid>>1 (32 rows), wn=wid&1 (64 cols).
// Per chunk: issue 24 HMMA (zeroed accW), gen next chunk's A while tensor
// drains, then flush accW->accT (RN adds). One barrier per chunk.
__global__ void __launch_bounds__(256, 1) layer_mma_kernel(
    const float* __restrict__ X, const char* __restrict__ Wg,
    const float* __restrict__ grid, float* __restrict__ Y)
{
    extern __shared__ char smem[];
    const uint32_t Abase = smem_u32(smem);
    const uint32_t Wbase = Abase + WOFF;

    const int tid = threadIdx.x;
    const int wid = tid >> 5, lane = tid & 31;
    const int wm = wid >> 1, wn = wid & 1;
    const size_t row0 = (size_t)blockIdx.x * BM;

    const float g0   = grid[0];
    const float invh = 1.0f / (grid[1] - grid[0]);

    // prologue: gen A(0) into buf 0; prefetch W(0) into buf 0
    gen_chunk(0, smem, X, row0, tid, g0, invh);
    for (int i = tid; i < WBLOB / 16; i += 256)
        cp16(Wbase + i * 16, Wg + i * 16);
    asm volatile("cp.async.commit_group;");
    __syncthreads();

    float accT[2][8][4];
#pragma unroll
    for (int mt = 0; mt < 2; ++mt)
#pragma unroll
        for (int nt = 0; nt < 8; ++nt)
#pragma unroll
            for (int e = 0; e < 4; ++e) accT[mt][nt][e] = 0.0f;

    // per-thread ldmatrix geometry
    const uint32_t aGeo = (wm * 32 + (lane & 15)) * ASTR + (lane >> 4) * 16;
    const uint32_t wCol = wn * 128 + (lane >> 4) * 16;
    const uint32_t wRow = (uint32_t)(lane & 15) * WSTR;

    for (int c = 0; c < NCH; ++c) {
        const int b = c & 1;

        // prefetch W(c+1) into other buffer; ensure W(c) resident
        if (c + 1 < NCH) {
            const char* src = Wg + (size_t)(c + 1) * WBLOB;
            uint32_t dst = Wbase + (b ^ 1) * WBLOB;
            for (int i = tid; i < WBLOB / 16; i += 256)
                cp16(dst + i * 16, src + i * 16);
            asm volatile("cp.async.commit_group;");
            asm volatile("cp.async.wait_group 1;");
        } else {
            asm volatile("cp.async.wait_group 0;");
        }

        // ---- issue MMAs for chunk c (zeroed accW) ----
        float accW[2][8][4];
#pragma unroll
        for (int mt = 0; mt < 2; ++mt)
#pragma unroll
            for (int nt = 0; nt < 8; ++nt)
#pragma unroll
                for (int e = 0; e < 4; ++e) accW[mt][nt][e] = 0.0f;

        const uint32_t Ab_ = Abase + b * ABUF;
        const uint32_t Wb  = Wbase + b * WBLOB;
#pragma unroll
        for (int ks = 0; ks < 4; ++ks) {
            uint32_t ah[2][4], am[2][4], al[2][4];
#pragma unroll
            for (int mt = 0; mt < 2; ++mt) {
                uint32_t a = Ab_ + aGeo + mt * (16 * ASTR) + ks * 32;
                ldm_x4(ah[mt], a);
                ldm_x4(am[mt], a + ATILE);
                ldm_x4(al[mt], a + 2 * ATILE);
            }
#pragma unroll
            for (int g = 0; g < 4; ++g) {
                uint32_t wh[4], wmr[4], wl[4];
                uint32_t a = Wb + wRow + ks * (16 * WSTR) + wCol + g * 32;
                ldm_x4t(wh,  a);
                ldm_x4t(wmr, a + WIMG);
                ldm_x4t(wl,  a + 2 * WIMG);
#pragma unroll
                for (int mt = 0; mt < 2; ++mt) {
                    float* a0 = accW[mt][2 * g];
                    float* a1 = accW[mt][2 * g + 1];
                    mma16816(a0, ah[mt], wh);       mma16816(a1, ah[mt], wh + 2);
                    mma16816(a0, ah[mt], wmr);      mma16816(a1, ah[mt], wmr + 2);
                    mma16816(a0, am[mt], wh);       mma16816(a1, am[mt], wh + 2);
                    mma16816(a0, am[mt], wmr);      mma16816(a1, am[mt], wmr + 2);
                    mma16816(a0, ah[mt], wl);       mma16816(a1, ah[mt], wl + 2);
                    mma16816(a0, al[mt], wh);       mma16816(a1, al[mt], wh + 2);
                }
            }
        }

        // ---- gen A(c+1) into other buffer (overlaps tensor drain) ----
        if (c + 1 < NCH)
            gen_chunk(c + 1, smem + (b ^ 1) * ABUF, X, row0, tid, g0, invh);

        // ---- flush chunk into total (first FADD waits on MMA results) ----
#pragma unroll
        for (int mt = 0; mt < 2; ++mt)
#pragma unroll
            for (int nt = 0; nt < 8; ++nt)
#pragma unroll
                for (int e = 0; e < 4; ++e) accT[mt][nt][e] += accW[mt][nt][e];

        __syncthreads();   // A[b] free for gen(c+2); gen(c+1) visible to all
    }

    // ---- epilogue: fragment -> gmem ----
#pragma unroll
    for (int mt = 0; mt < 2; ++mt) {
        size_t row = row0 + wm * 32 + mt * 16 + (lane >> 2);
#pragma unroll
        for (int nt = 0; nt < 8; ++nt) {
            int col = wn * 64 + nt * 8 + (lane & 3) * 2;
            *(float2*)&Y[row * HID + col]       = make_float2(accT[mt][nt][0], accT[mt][nt][1]);
            *(float2*)&Y[(row + 8) * HID + col] = make_float2(accT[mt][nt][2], accT[mt][nt][3]);
        }
    }
}

// ---------------- argmax of dot(e, pn) (== argmax cosine sim) ---------------
#define AR 64
#define AC 64
__global__ void __launch_bounds__(256, 1) assign_kernel(
    const float* __restrict__ E, const float* __restrict__ Pn,
    int Kp, float* __restrict__ outA)
{
    extern __shared__ float sm[];
    float* sE   = sm;
    float* sP   = sE + AR * HID;
    float* sVal = sP + AC * HID;
    int*   sIdx = (int*)(sVal + AR * 16);

    const int tid = threadIdx.x;
    const size_t row0 = (size_t)blockIdx.x * AR;
    const int ty = tid >> 4, tx = tid & 15;

    {
        const float4* Ev = (const float4*)(E + row0 * HID);
        float4* sEv = (float4*)sE;
#pragma unroll
        for (int it = 0; it < (AR * HID / 4) / 256; ++it)
            sEv[tid + it * 256] = Ev[tid + it * 256];
    }

    float best[4]; int bidx[4];
#pragma unroll
    for (int r = 0; r < 4; ++r) { best[r] = -3.0e38f; bidx[r] = 0; }

    const int sws = (tx & 7) << 2;

    for (int pc = 0; pc < Kp / AC; ++pc) {
        __syncthreads();
#pragma unroll
        for (int it = 0; it < (AC * HID / 4) / 256; ++it) {
            int t  = tid + it * 256;
            int p  = t & (AC - 1);
            int k0 = (t >> 6) << 2;
            float4 v = *(const float4*)(Pn + (size_t)(pc * AC + p) * HID + k0);
            int sw = ((p >> 2) & 7) << 2;
            *(float4*)(sP + p * HID + (k0 ^ sw)) = v;
        }
        __syncthreads();

        float acc[4][4];
#pragma unroll
        for (int r = 0; r < 4; ++r)
#pragma unroll
            for (int c = 0; c < 4; ++c) acc[r][c] = 0.0f;

#pragma unroll 4
        for (int k = 0; k < HID; k += 4) {
            float4 a[4], pv[4];
#pragma unroll
            for (int r = 0; r < 4; ++r)
                a[r] = *(const float4*)(sE + (ty * 4 + r) * HID + k);
#pragma unroll
            for (int c = 0; c < 4; ++c)
                pv[c] = *(const float4*)(sP + (tx * 4 + c) * HID + (k ^ sws));
#pragma unroll
            for (int r = 0; r < 4; ++r)
#pragma unroll
                for (int c = 0; c < 4; ++c)
                    acc[r][c] += a[r].x * pv[c].x + a[r].y * pv[c].y
                               + a[r].z * pv[c].z + a[r].w * pv[c].w;
        }
#pragma unroll
        for (int c = 0; c < 4; ++c) {
            int idx = pc * AC + tx * 4 + c;
#pragma unroll
            for (int r = 0; r < 4; ++r)
                if (acc[r][c] > best[r]) { best[r] = acc[r][c]; bidx[r] = idx; }
        }
    }
    __syncthreads();
#pragma unroll
    for (int r = 0; r < 4; ++r) {
        sVal[(ty * 4 + r) * 16 + tx] = best[r];
        sIdx[(ty * 4 + r) * 16 + tx] = bidx[r];
    }
    __syncthreads();
    if (tid < AR) {
        float bv = -3.0e38f; int bi = 0x7fffffff;
#pragma unroll
        for (int t = 0; t < 16; ++t) {
            float v = sVal[tid * 16 + t];
            int   i = sIdx[tid * 16 + t];
            if (v > bv || (v == bv && i < bi)) { bv = v; bi = i; }
        }
        outA[row0 + tid] = (float)bi;
    }
}

// ---------------- launch ----------------------------------------------------
extern "C" void kernel_launch(void* const* d_in, const int* in_sizes, int n_in,
                              void* d_out, int out_size)
{
    const float* x    = (const float*)d_in[0];
    const float* prot = (const float*)d_in[1];
    const float* grid = (const float*)d_in[2];
    const float* bw1  = (const float*)d_in[3];
    const float* sw1  = (const float*)d_in[4];
    const float* sc1  = (const float*)d_in[5];
    const float* bw2  = (const float*)d_in[6];
    const float* sw2  = (const float*)d_in[7];
    const float* sc2  = (const float*)d_in[8];
    float* out = (float*)d_out;

    const int N  = in_sizes[0] / HID;
    const int Kp = in_sizes[1] / HID;

    uint4 *W1, *W2; float *h, *pn;
    cudaGetSymbolAddress((void**)&W1, g_W1);
    cudaGetSymbolAddress((void**)&W2, g_W2);
    cudaGetSymbolAddress((void**)&h,  g_h);
    cudaGetSymbolAddress((void**)&pn, g_pn);

    const int SMEM_ASSIGN = (AR * HID + AC * HID + AR * 16 + AR * 16) * 4;    // 72 KB
    cudaFuncSetAttribute(layer_mma_kernel, cudaFuncAttributeMaxDynamicSharedMemorySize, SMEM_LAYER);
    cudaFuncSetAttribute(assign_kernel,    cudaFuncAttributeMaxDynamicSharedMemorySize, SMEM_ASSIGN);

    const int wtasks = NCH * 64 * HID;
    prep_w_kernel<<<(wtasks + 255) / 256, 256>>>(bw1, sw1, sc1, (char*)W1);
    prep_w_kernel<<<(wtasks + 255) / 256, 256>>>(bw2, sw2, sc2, (char*)W2);
    prep_p_kernel<<<Kp, HID>>>(prot, pn);

    layer_mma_kernel<<<N / BM, 256, SMEM_LAYER>>>(x, (const char*)W1, grid, h);
    layer_mma_kernel<<<N / BM, 256, SMEM_LAYER>>>(h, (const char*)W2, grid, out);

    if ((size_t)out_size >= (size_t)N * HID + (size_t)N)
        assign_kernel<<<N / AR, 256, SMEM_ASSIGN>>>(out, pn, Kp, out + (size_t)N * HID);
}

// round 12
// speedup vs baseline: 1.7360x; 1.2649x over previous
#include <cuda_runtime.h>
#include <cuda_fp16.h>
#include <math.h>
#include <cstdint>

#define HID   128
#define NCH   18                 // 2 silu chunks + 16 spline chunks, 64 k each
#define BM    128
#define NMAX  131072
#define KPMAX 256

#define ASTR  144                // A row stride bytes (64 k * 2B + 16B pad)
#define ATILE 18432              // 128 * 144 (one image)
#define ABUF  (2 * ATILE)        // 36864: hi | mid
#define WSTR  272                // W k-row stride bytes (128 o * 2B + 16B pad)
#define WIMG  17408              // 64 * 272 (one image)
#define WBLOB (2 * WIMG)         // 34816: hi | mid
#define WOFF  (2 * ABUF)         // 73728
#define SMEM_LAYER (WOFF + 2 * WBLOB)   // 143360

// ---------------- scratch (device globals; no allocation allowed) ----------
__device__ uint4 g_W1[(NCH * WBLOB) / 16];
__device__ uint4 g_W2[(NCH * WBLOB) / 16];
__device__ float g_h[(size_t)NMAX * HID];
__device__ float g_pn[KPMAX * HID];

// ---------------- PTX helpers (sm_80-portable; no tcgen05) ------------------
__device__ __forceinline__ uint32_t smem_u32(const void* p) {
    uint32_t a;
    asm("{ .reg .u64 t; cvta.to.shared.u64 t, %1; cvt.u32.u64 %0, t; }" : "=r"(a) : "l"(p));
    return a;
}
__device__ __forceinline__ void ldm_x4(uint32_t* r, uint32_t a) {
    asm volatile("ldmatrix.sync.aligned.m8n8.x4.shared.b16 {%0,%1,%2,%3}, [%4];"
        : "=r"(r[0]), "=r"(r[1]), "=r"(r[2]), "=r"(r[3]) : "r"(a));
}
__device__ __forceinline__ void ldm_x4t(uint32_t* r, uint32_t a) {
    asm volatile("ldmatrix.sync.aligned.m8n8.x4.trans.shared.b16 {%0,%1,%2,%3}, [%4];"
        : "=r"(r[0]), "=r"(r[1]), "=r"(r[2]), "=r"(r[3]) : "r"(a));
}
// fp16 inputs, fp32 accumulator (11-bit mantissa => 2-way split reaches 2^-22)
__device__ __forceinline__ void mma16816(float* d, const uint32_t* a, const uint32_t* b) {
    asm volatile("mma.sync.aligned.m16n8k16.row.col.f32.f16.f16.f32 "
        "{%0,%1,%2,%3}, {%4,%5,%6,%7}, {%8,%9}, {%0,%1,%2,%3};"
        : "+f"(d[0]), "+f"(d[1]), "+f"(d[2]), "+f"(d[3])
        : "r"(a[0]), "r"(a[1]), "r"(a[2]), "r"(a[3]), "r"(b[0]), "r"(b[1]));
}
__device__ __forceinline__ void cp16(uint32_t saddr, const void* gaddr) {
    asm volatile("cp.async.cg.shared.global [%0], [%1], 16;" :: "r"(saddr), "l"(gaddr));
}

// ---------------- 2-way fp16 split (eps ~ 2^-22) ----------------------------
__device__ __forceinline__ void split2(float a, __half& h, __half& m) {
    h = __float2half_rn(a);
    m = __float2half_rn(a - __half2float(h));
}

// ---------------- weight prep: k-major fp16 hi/mid images -------------------
__global__ void prep_w_kernel(const float* __restrict__ bw,
                              const float* __restrict__ sw,
                              const float* __restrict__ sc,
                              char* __restrict__ Wout)
{
    int idx = blockIdx.x * 256 + threadIdx.x;      // (chunk, k, o)
    if (idx >= NCH * 64 * HID) return;
    int chunk = idx / (64 * HID);
    int rem   = idx - chunk * (64 * HID);
    int k = rem >> 7, o = rem & 127;
    float w;
    if (chunk < 2) {
        w = bw[o * HID + chunk * 64 + k];
    } else {
        int f = (chunk - 2) * 8 + (k >> 3);
        w = sw[(o * HID + f) * 8 + (k & 7)] * sc[o * HID + f];
    }
    __half h, m;
    split2(w, h, m);
    char* base = Wout + (size_t)chunk * WBLOB + k * WSTR + o * 2;
    *(__half*)(base)        = h;
    *(__half*)(base + WIMG) = m;
}

// ---------------- prototype normalization ----------------------------------
__global__ void prep_p_kernel(const float* __restrict__ P, float* __restrict__ Pn)
{
    int r = blockIdx.x, t = threadIdx.x;
    float v = P[r * HID + t];
    float s = v * v;
#pragma unroll
    for (int o = 16; o > 0; o >>= 1) s += __shfl_xor_sync(0xffffffffu, s, o);
    __shared__ float red[4];
    if ((t & 31) == 0) red[t >> 5] = s;
    __syncthreads();
    float nrm = fmaxf(sqrtf(red[0] + red[1] + red[2] + red[3]), 1e-8f);
    Pn[r * HID + t] = v / nrm;
}

// ---------------- A pack: 8 values -> fp16 hi/mid, 16B stores ---------------
__device__ __forceinline__ void store8(char* Ab, int r, int blk, const float* v)
{
    __half h[8], m[8];
#pragma unroll
    for (int e = 0; e < 8; ++e) split2(v[e], h[e], m[e]);
    uint32_t off = r * ASTR + blk * 16;
    *(uint4*)(Ab + off)         = *(uint4*)h;
    *(uint4*)(Ab + ATILE + off) = *(uint4*)m;
}

// ---------------- A-chunk generation (reads x from gmem/L2) -----------------
__device__ __forceinline__ void gen_chunk(int cc, char* Ab, const float* __restrict__ X,
                                          size_t row0, int tid, float g0, float invh)
{
    if (cc < 2) {
#pragma unroll
        for (int it = 0; it < 4; ++it) {
            int t = tid + it * 256;
            int r = t >> 3, blk = t & 7;
            const float4* xp = (const float4*)(X + (row0 + r) * HID + cc * 64 + blk * 8);
            float4 x0 = xp[0], x1 = xp[1];
            float v[8] = {x0.x, x0.y, x0.z, x0.w, x1.x, x1.y, x1.z, x1.w};
#pragma unroll
            for (int e = 0; e < 8; ++e) {
                float x = v[e];
                v[e] = x / (1.0f + __expf(-x));
            }
            store8(Ab, r, blk, v);
        }
    } else {
        const int f0 = (cc - 2) * 8;
#pragma unroll
        for (int it = 0; it < 4; ++it) {
            int t = tid + it * 256;
            int r = t >> 3, fl = t & 7;
            float x = X[(row0 + r) * HID + f0 + fl];
            float tt = (x - g0) * invh;              // uniform-grid cubic B-spline
            float fi = floorf(tt);
            int   i  = (int)fi;
            float u  = tt - fi;
            float u2 = u * u, u3 = u2 * u, om = 1.0f - u;
            float c0v = u3 * (1.0f / 6.0f);
            float c1v = (1.0f / 6.0f) * (1.0f + 3.0f * u + 3.0f * u2 - 3.0f * u3);
            float c2v = (1.0f / 6.0f) * (4.0f - 6.0f * u2 + 3.0f * u3);
            float c3v = om * om * om * (1.0f / 6.0f);
            float v[8];
#pragma unroll
            for (int j = 0; j < 8; ++j) {
                int mm_ = i - j;
                float val = 0.0f;
                val = (mm_ == 0) ? c0v : val;
                val = (mm_ == 1) ? c1v : val;
                val = (mm_ == 2) ? c2v : val;
                val = (mm_ == 3) ? c3v : val;
                v[j] = val;
            }
            store8(Ab, r, fl, v);
        }
    }
}

// ---------------- fused KAN layer on HMMA (fp16x2, 4 products) --------------
// CTA: 128 rows x 128 outs. 8 warps: wm=wid>>1 (32 rows), wn=wid&1 (64 cols).
// D_chunk = Ah*Wh + Ah*Wm + Am*Wh + Am*Wm  (fp16 split: residual ~2^-22 —
// below the flip threshold; bf16's 2^-16 residual flips near-tie argmaxes).
// Zeroed accW per chunk, RN flush into accT (kills RZ chain bias).
// Race-safe: barrier after cp.async.wait_group.
__global__ void __launch_bounds__(256, 1) layer_mma_kernel(
    const float* __restrict__ X, const char* __restrict__ Wg,
    const float* __restrict__ grid, float* __restrict__ Y)
{
    extern __shared__ char smem[];
    const uint32_t Abase = smem_u32(smem);
    const uint32_t Wbase = Abase + WOFF;

    const int tid = threadIdx.x;
    const int wid = tid >> 5, lane = tid & 31;
    const int wm = wid >> 1, wn = wid & 1;
    const size_t row0 = (size_t)blockIdx.x * BM;

    const float g0   = grid[0];
    const float invh = 1.0f / (grid[1] - grid[0]);

    // prologue: gen A(0) into buf 0; prefetch W(0) into buf 0
    gen_chunk(0, smem, X, row0, tid, g0, invh);
    for (int i = tid; i < WBLOB / 16; i += 256)
        cp16(Wbase + i * 16, Wg + i * 16);
    asm volatile("cp.async.commit_group;");

    float accT[2][8][4];
#pragma unroll
    for (int mt = 0; mt < 2; ++mt)
#pragma unroll
        for (int nt = 0; nt < 8; ++nt)
#pragma unroll
            for (int e = 0; e < 4; ++e) accT[mt][nt][e] = 0.0f;

    // per-thread ldmatrix geometry
    const uint32_t aGeo = (wm * 32 + (lane & 15)) * ASTR + (lane >> 4) * 16;
    const uint32_t wCol = wn * 128 + (lane >> 4) * 16;
    const uint32_t wRow = (uint32_t)(lane & 15) * WSTR;

    for (int c = 0; c < NCH; ++c) {
        const int b = c & 1;

        // issue prefetch W(c+1) into other buffer (safe: last read of that
        // buffer was before the previous iteration's trailing barrier)
        if (c + 1 < NCH) {
            const char* src = Wg + (size_t)(c + 1) * WBLOB;
            uint32_t dst = Wbase + (b ^ 1) * WBLOB;
            for (int i = tid; i < WBLOB / 16; i += 256)
                cp16(dst + i * 16, src + i * 16);
            asm volatile("cp.async.commit_group;");
            asm volatile("cp.async.wait_group 1;");
        } else {
            asm volatile("cp.async.wait_group 0;");
        }
        __syncthreads();   // ALL threads' W(c) copies complete; A(c) visible

        // ---- issue MMAs for chunk c (zeroed accW) ----
        float accW[2][8][4];
#pragma unroll
        for (int mt = 0; mt < 2; ++mt)
#pragma unroll
            for (int nt = 0; nt < 8; ++nt)
#pragma unroll
                for (int e = 0; e < 4; ++e) accW[mt][nt][e] = 0.0f;

        const uint32_t Ab_ = Abase + b * ABUF;
        const uint32_t Wb  = Wbase + b * WBLOB;
#pragma unroll
        for (int ks = 0; ks < 4; ++ks) {
            uint32_t ah[2][4], am[2][4];
#pragma unroll
            for (int mt = 0; mt < 2; ++mt) {
                uint32_t a = Ab_ + aGeo + mt * (16 * ASTR) + ks * 32;
                ldm_x4(ah[mt], a);
                ldm_x4(am[mt], a + ATILE);
            }
#pragma unroll
            for (int g = 0; g < 4; ++g) {
                uint32_t wh[4], wmr[4];
                uint32_t a = Wb + wRow + ks * (16 * WSTR) + wCol + g * 32;
                ldm_x4t(wh,  a);
                ldm_x4t(wmr, a + WIMG);
#pragma unroll
                for (int mt = 0; mt < 2; ++mt) {
                    float* a0 = accW[mt][2 * g];
                    float* a1 = accW[mt][2 * g + 1];
                    mma16816(a0, ah[mt], wh);       mma16816(a1, ah[mt], wh + 2);
                    mma16816(a0, ah[mt], wmr);      mma16816(a1, ah[mt], wmr + 2);
                    mma16816(a0, am[mt], wh);       mma16816(a1, am[mt], wh + 2);
                    mma16816(a0, am[mt], wmr);      mma16816(a1, am[mt], wmr + 2);
                }
            }
        }

        // ---- gen A(c+1) into other buffer (overlaps tensor drain) ----
        if (c + 1 < NCH)
            gen_chunk(c + 1, smem + (b ^ 1) * ABUF, X, row0, tid, g0, invh);

        // ---- flush chunk into total (first FADD waits on MMA results) ----
#pragma unroll
        for (int mt = 0; mt < 2; ++mt)
#pragma unroll
            for (int nt = 0; nt < 8; ++nt)
#pragma unroll
                for (int e = 0; e < 4; ++e) accT[mt][nt][e] += accW[mt][nt][e];

        __syncthreads();   // A(c+1) visible; A/W bufs free for next iteration
    }

    // ---- epilogue: fragment -> gmem ----
#pragma unroll
    for (int mt = 0; mt < 2; ++mt) {
        size_t row = row0 + wm * 32 + mt * 16 + (lane >> 2);
#pragma unroll
        for (int nt = 0; nt < 8; ++nt) {
            int col = wn * 64 + nt * 8 + (lane & 3) * 2;
            *(float2*)&Y[row * HID + col]       = make_float2(accT[mt][nt][0], accT[mt][nt][1]);
            *(float2*)&Y[(row + 8) * HID + col] = make_float2(accT[mt][nt][2], accT[mt][nt][3]);
        }
    }
}

// ---------------- argmax of dot(e, pn) (== argmax cosine sim) ---------------
#define AR 64
#define AC 64
__global__ void __launch_bounds__(256, 1) assign_kernel(
    const float* __restrict__ E, const float* __restrict__ Pn,
    int Kp, float* __restrict__ outA)
{
    extern __shared__ float sm[];
    float* sE   = sm;
    float* sP   = sE + AR * HID;
    float* sVal = sP + AC * HID;
    int*   sIdx = (int*)(sVal + AR * 16);

    const int tid = threadIdx.x;
    const size_t row0 = (size_t)blockIdx.x * AR;
    const int ty = tid >> 4, tx = tid & 15;

    {
        const float4* Ev = (const float4*)(E + row0 * HID);
        float4* sEv = (float4*)sE;
#pragma unroll
        for (int it = 0; it < (AR * HID / 4) / 256; ++it)
            sEv[tid + it * 256] = Ev[tid + it * 256];
    }

    float best[4]; int bidx[4];
#pragma unroll
    for (int r = 0; r < 4; ++r) { best[r] = -3.0e38f; bidx[r] = 0; }

    const int sws = (tx & 7) << 2;

    for (int pc = 0; pc < Kp / AC; ++pc) {
        __syncthreads();
#pragma unroll
        for (int it = 0; it < (AC * HID / 4) / 256; ++it) {
            int t  = tid + it * 256;
            int p  = t & (AC - 1);
            int k0 = (t >> 6) << 2;
            float4 v = *(const float4*)(Pn + (size_t)(pc * AC + p) * HID + k0);
            int sw = ((p >> 2) & 7) << 2;
            *(float4*)(sP + p * HID + (k0 ^ sw)) = v;
        }
        __syncthreads();

        float acc[4][4];
#pragma unroll
        for (int r = 0; r < 4; ++r)
#pragma unroll
            for (int c = 0; c < 4; ++c) acc[r][c] = 0.0f;

#pragma unroll 4
        for (int k = 0; k < HID; k += 4) {
            float4 a[4], pv[4];
#pragma unroll
            for (int r = 0; r < 4; ++r)
                a[r] = *(const float4*)(sE + (ty * 4 + r) * HID + k);
#pragma unroll
            for (int c = 0; c < 4; ++c)
                pv[c] = *(const float4*)(sP + (tx * 4 + c) * HID + (k ^ sws));
#pragma unroll
            for (int r = 0; r < 4; ++r)
#pragma unroll
                for (int c = 0; c < 4; ++c)
                    acc[r][c] += a[r].x * pv[c].x + a[r].y * pv[c].y
                               + a[r].z * pv[c].z + a[r].w * pv[c].w;
        }
#pragma unroll
        for (int c = 0; c < 4; ++c) {
            int idx = pc * AC + tx * 4 + c;
#pragma unroll
            for (int r = 0; r < 4; ++r)
                if (acc[r][c] > best[r]) { best[r] = acc[r][c]; bidx[r] = idx; }
        }
    }
    __syncthreads();
#pragma unroll
    for (int r = 0; r < 4; ++r) {
        sVal[(ty * 4 + r) * 16 + tx] = best[r];
        sIdx[(ty * 4 + r) * 16 + tx] = bidx[r];
    }
    __syncthreads();
    if (tid < AR) {
        float bv = -3.0e38f; int bi = 0x7fffffff;
#pragma unroll
        for (int t = 0; t < 16; ++t) {
            float v = sVal[tid * 16 + t];
            int   i = sIdx[tid * 16 + t];
            if (v > bv || (v == bv && i < bi)) { bv = v; bi = i; }
        }
        outA[row0 + tid] = (float)bi;
    }
}

// ---------------- launch ----------------------------------------------------
extern "C" void kernel_launch(void* const* d_in, const int* in_sizes, int n_in,
                              void* d_out, int out_size)
{
    const float* x    = (const float*)d_in[0];
    const float* prot = (const float*)d_in[1];
    const float* grid = (const float*)d_in[2];
    const float* bw1  = (const float*)d_in[3];
    const float* sw1  = (const float*)d_in[4];
    const float* sc1  = (const float*)d_in[5];
    const float* bw2  = (const float*)d_in[6];
    const float* sw2  = (const float*)d_in[7];
    const float* sc2  = (const float*)d_in[8];
    float* out = (float*)d_out;

    const int N  = in_sizes[0] / HID;
    const int Kp = in_sizes[1] / HID;

    uint4 *W1, *W2; float *h, *pn;
    cudaGetSymbolAddress((void**)&W1, g_W1);
    cudaGetSymbolAddress((void**)&W2, g_W2);
    cudaGetSymbolAddress((void**)&h,  g_h);
    cudaGetSymbolAddress((void**)&pn, g_pn);

    const int SMEM_ASSIGN = (AR * HID + AC * HID + AR * 16 + AR * 16) * 4;    // 72 KB
    cudaFuncSetAttribute(layer_mma_kernel, cudaFuncAttributeMaxDynamicSharedMemorySize, SMEM_LAYER);
    cudaFuncSetAttribute(assign_kernel,    cudaFuncAttributeMaxDynamicSharedMemorySize, SMEM_ASSIGN);

    const int wtasks = NCH * 64 * HID;
    prep_w_kernel<<<(wtasks + 255) / 256, 256>>>(bw1, sw1, sc1, (char*)W1);
    prep_w_kernel<<<(wtasks + 255) / 256, 256>>>(bw2, sw2, sc2, (char*)W2);
    prep_p_kernel<<<Kp, HID>>>(prot, pn);

    layer_mma_kernel<<<N / BM, 256, SMEM_LAYER>>>(x, (const char*)W1, grid, h);
    layer_mma_kernel<<<N / BM, 256, SMEM_LAYER>>>(h, (const char*)W2, grid, out);

    if ((size_t)out_size >= (size_t)N * HID + (size_t)N)
        assign_kernel<<<N / AR, 256, SMEM_ASSIGN>>>(out, pn, Kp, out + (size_t)N * HID);
}

// round 13
// speedup vs baseline: 2.1003x; 1.2098x over previous
#include <cuda_runtime.h>
#include <cuda_fp16.h>
#include <math.h>
#include <cstdint>

#define HID   128
#define NCH   18                 // 2 silu chunks + 16 spline chunks, 64 k each
#define BM    128
#define NMAX  131072
#define KPMAX 256

#define ASTR  144                // A row stride bytes (64 k * 2B + 16B pad)
#define ATILE 18432              // 128 * 144 (one image)
#define ABUF  (2 * ATILE)        // 36864: hi | mid
#define WSTR  272                // W k-row stride bytes (128 o * 2B + 16B pad)
#define WIMG  17408              // 64 * 272 (one image)
#define WBLOB (2 * WIMG)         // 34816: hi | mid
#define WOFF  (2 * ABUF)         // 73728
#define SMEM_LAYER (WOFF + 2 * WBLOB)   // 143360

// assign kernel layout
#define PSTR  528                // proto k-row stride (256 protos * 2B + 16 pad)
#define PIMG  67584              // 128 * 528 (one image)
#define ESTR  272                // E row stride (128 k * 2B + 16 pad)
#define EIMG  34816              // 128 * 272
#define EOFF  (2 * PIMG)         // 135168
#define SMEM_ASSIGN (EOFF + 2 * EIMG)   // 204800

// ---------------- scratch (device globals; no allocation allowed) ----------
__device__ uint4 g_W1[(NCH * WBLOB) / 16];
__device__ uint4 g_W2[(NCH * WBLOB) / 16];
__device__ float g_h[(size_t)NMAX * HID];
__device__ uint4 g_ps[(2 * PIMG) / 16];   // pre-split normalized protos (hi|mid)

// ---------------- PTX helpers (sm_80-portable; no tcgen05) ------------------
__device__ __forceinline__ uint32_t smem_u32(const void* p) {
    uint32_t a;
    asm("{ .reg .u64 t; cvta.to.shared.u64 t, %1; cvt.u32.u64 %0, t; }" : "=r"(a) : "l"(p));
    return a;
}
__device__ __forceinline__ void ldm_x4(uint32_t* r, uint32_t a) {
    asm volatile("ldmatrix.sync.aligned.m8n8.x4.shared.b16 {%0,%1,%2,%3}, [%4];"
        : "=r"(r[0]), "=r"(r[1]), "=r"(r[2]), "=r"(r[3]) : "r"(a));
}
__device__ __forceinline__ void ldm_x4t(uint32_t* r, uint32_t a) {
    asm volatile("ldmatrix.sync.aligned.m8n8.x4.trans.shared.b16 {%0,%1,%2,%3}, [%4];"
        : "=r"(r[0]), "=r"(r[1]), "=r"(r[2]), "=r"(r[3]) : "r"(a));
}
// fp16 inputs, fp32 accumulator (11-bit mantissa => 2-way split reaches 2^-22)
__device__ __forceinline__ void mma16816(float* d, const uint32_t* a, const uint32_t* b) {
    asm volatile("mma.sync.aligned.m16n8k16.row.col.f32.f16.f16.f32 "
        "{%0,%1,%2,%3}, {%4,%5,%6,%7}, {%8,%9}, {%0,%1,%2,%3};"
        : "+f"(d[0]), "+f"(d[1]), "+f"(d[2]), "+f"(d[3])
        : "r"(a[0]), "r"(a[1]), "r"(a[2]), "r"(a[3]), "r"(b[0]), "r"(b[1]));
}
__device__ __forceinline__ void cp16(uint32_t saddr, const void* gaddr) {
    asm volatile("cp.async.cg.shared.global [%0], [%1], 16;" :: "r"(saddr), "l"(gaddr));
}

// ---------------- 2-way fp16 split (eps ~ 2^-22) ----------------------------
__device__ __forceinline__ void split2(float a, __half& h, __half& m) {
    h = __float2half_rn(a);
    m = __float2half_rn(a - __half2float(h));
}

// ---------------- weight prep: k-major fp16 hi/mid images -------------------
__global__ void prep_w_kernel(const float* __restrict__ bw,
                              const float* __restrict__ sw,
                              const float* __restrict__ sc,
                              char* __restrict__ Wout)
{
    int idx = blockIdx.x * 256 + threadIdx.x;      // (chunk, k, o)
    if (idx >= NCH * 64 * HID) return;
    int chunk = idx / (64 * HID);
    int rem   = idx - chunk * (64 * HID);
    int k = rem >> 7, o = rem & 127;
    float w;
    if (chunk < 2) {
        w = bw[o * HID + chunk * 64 + k];
    } else {
        int f = (chunk - 2) * 8 + (k >> 3);
        w = sw[(o * HID + f) * 8 + (k & 7)] * sc[o * HID + f];
    }
    __half h, m;
    split2(w, h, m);
    char* base = Wout + (size_t)chunk * WBLOB + k * WSTR + o * 2;
    *(__half*)(base)        = h;
    *(__half*)(base + WIMG) = m;
}

// ---------------- prototype prep: normalize + split to k-major images -------
__global__ void prep_p_kernel(const float* __restrict__ P, char* __restrict__ Pout)
{
    int r = blockIdx.x, t = threadIdx.x;           // r = proto, t = k
    float v = P[r * HID + t];
    float s = v * v;
#pragma unroll
    for (int o = 16; o > 0; o >>= 1) s += __shfl_xor_sync(0xffffffffu, s, o);
    __shared__ float red[4];
    if ((t & 31) == 0) red[t >> 5] = s;
    __syncthreads();
    float nrm = fmaxf(sqrtf(red[0] + red[1] + red[2] + red[3]), 1e-8f);
    __half h, m;
    split2(v / nrm, h, m);
    char* base = Pout + t * PSTR + r * 2;
    *(__half*)(base)        = h;
    *(__half*)(base + PIMG) = m;
}

// ---------------- A pack: 8 values -> fp16 hi/mid, 16B stores ---------------
__device__ __forceinline__ void store8s(char* Ab, uint32_t off, int img_stride,
                                        const float* v)
{
    __half h[8], m[8];
#pragma unroll
    for (int e = 0; e < 8; ++e) split2(v[e], h[e], m[e]);
    *(uint4*)(Ab + off)              = *(uint4*)h;
    *(uint4*)(Ab + img_stride + off) = *(uint4*)m;
}

// ---------------- A-chunk generation (reads x from gmem/L2) -----------------
__device__ __forceinline__ void gen_chunk(int cc, char* Ab, const float* __restrict__ X,
                                          size_t row0, int tid, float g0, float invh)
{
    if (cc < 2) {
#pragma unroll
        for (int it = 0; it < 4; ++it) {
            int t = tid + it * 256;
            int r = t >> 3, blk = t & 7;
            const float4* xp = (const float4*)(X + (row0 + r) * HID + cc * 64 + blk * 8);
            float4 x0 = xp[0], x1 = xp[1];
            float v[8] = {x0.x, x0.y, x0.z, x0.w, x1.x, x1.y, x1.z, x1.w};
#pragma unroll
            for (int e = 0; e < 8; ++e) {
                float x = v[e];
                v[e] = x / (1.0f + __expf(-x));
            }
            store8s(Ab, r * ASTR + blk * 16, ATILE, v);
        }
    } else {
        const int f0 = (cc - 2) * 8;
#pragma unroll
        for (int it = 0; it < 4; ++it) {
            int t = tid + it * 256;
            int r = t >> 3, fl = t & 7;
            float x = X[(row0 + r) * HID + f0 + fl];
            float tt = (x - g0) * invh;              // uniform-grid cubic B-spline
            float fi = floorf(tt);
            int   i  = (int)fi;
            float u  = tt - fi;
            float u2 = u * u, u3 = u2 * u, om = 1.0f - u;
            float c0v = u3 * (1.0f / 6.0f);
            float c1v = (1.0f / 6.0f) * (1.0f + 3.0f * u + 3.0f * u2 - 3.0f * u3);
            float c2v = (1.0f / 6.0f) * (4.0f - 6.0f * u2 + 3.0f * u3);
            float c3v = om * om * om * (1.0f / 6.0f);
            float v[8];
#pragma unroll
            for (int j = 0; j < 8; ++j) {
                int mm_ = i - j;
                float val = 0.0f;
                val = (mm_ == 0) ? c0v : val;
                val = (mm_ == 1) ? c1v : val;
                val = (mm_ == 2) ? c2v : val;
                val = (mm_ == 3) ? c3v : val;
                v[j] = val;
            }
            store8s(Ab, r * ASTR + fl * 16, ATILE, v);
        }
    }
}

// ---------------- fused KAN layer on HMMA (fp16x2, 4 products) --------------
__global__ void __launch_bounds__(256, 1) layer_mma_kernel(
    const float* __restrict__ X, const char* __restrict__ Wg,
    const float* __restrict__ grid, float* __restrict__ Y)
{
    extern __shared__ char smem[];
    const uint32_t Abase = smem_u32(smem);
    const uint32_t Wbase = Abase + WOFF;

    const int tid = threadIdx.x;
    const int wid = tid >> 5, lane = tid & 31;
    const int wm = wid >> 1, wn = wid & 1;
    const size_t row0 = (size_t)blockIdx.x * BM;

    const float g0   = grid[0];
    const float invh = 1.0f / (grid[1] - grid[0]);

    gen_chunk(0, smem, X, row0, tid, g0, invh);
    for (int i = tid; i < WBLOB / 16; i += 256)
        cp16(Wbase + i * 16, Wg + i * 16);
    asm volatile("cp.async.commit_group;");

    float accT[2][8][4];
#pragma unroll
    for (int mt = 0; mt < 2; ++mt)
#pragma unroll
        for (int nt = 0; nt < 8; ++nt)
#pragma unroll
            for (int e = 0; e < 4; ++e) accT[mt][nt][e] = 0.0f;

    const uint32_t aGeo = (wm * 32 + (lane & 15)) * ASTR + (lane >> 4) * 16;
    const uint32_t wCol = wn * 128 + (lane >> 4) * 16;
    const uint32_t wRow = (uint32_t)(lane & 15) * WSTR;

    for (int c = 0; c < NCH; ++c) {
        const int b = c & 1;

        if (c + 1 < NCH) {
            const char* src = Wg + (size_t)(c + 1) * WBLOB;
            uint32_t dst = Wbase + (b ^ 1) * WBLOB;
            for (int i = tid; i < WBLOB / 16; i += 256)
                cp16(dst + i * 16, src + i * 16);
            asm volatile("cp.async.commit_group;");
            asm volatile("cp.async.wait_group 1;");
        } else {
            asm volatile("cp.async.wait_group 0;");
        }
        __syncthreads();   // ALL threads' W(c) copies complete; A(c) visible

        float accW[2][8][4];
#pragma unroll
        for (int mt = 0; mt < 2; ++mt)
#pragma unroll
            for (int nt = 0; nt < 8; ++nt)
#pragma unroll
                for (int e = 0; e < 4; ++e) accW[mt][nt][e] = 0.0f;

        const uint32_t Ab_ = Abase + b * ABUF;
        const uint32_t Wb  = Wbase + b * WBLOB;
#pragma unroll
        for (int ks = 0; ks < 4; ++ks) {
            uint32_t ah[2][4], am[2][4];
#pragma unroll
            for (int mt = 0; mt < 2; ++mt) {
                uint32_t a = Ab_ + aGeo + mt * (16 * ASTR) + ks * 32;
                ldm_x4(ah[mt], a);
                ldm_x4(am[mt], a + ATILE);
            }
#pragma unroll
            for (int g = 0; g < 4; ++g) {
                uint32_t wh[4], wmr[4];
                uint32_t a = Wb + wRow + ks * (16 * WSTR) + wCol + g * 32;
                ldm_x4t(wh,  a);
                ldm_x4t(wmr, a + WIMG);
#pragma unroll
                for (int mt = 0; mt < 2; ++mt) {
                    float* a0 = accW[mt][2 * g];
                    float* a1 = accW[mt][2 * g + 1];
                    mma16816(a0, ah[mt], wh);       mma16816(a1, ah[mt], wh + 2);
                    mma16816(a0, ah[mt], wmr);      mma16816(a1, ah[mt], wmr + 2);
                    mma16816(a0, am[mt], wh);       mma16816(a1, am[mt], wh + 2);
                    mma16816(a0, am[mt], wmr);      mma16816(a1, am[mt], wmr + 2);
                }
            }
        }

        if (c + 1 < NCH)
            gen_chunk(c + 1, smem + (b ^ 1) * ABUF, X, row0, tid, g0, invh);

#pragma unroll
        for (int mt = 0; mt < 2; ++mt)
#pragma unroll
            for (int nt = 0; nt < 8; ++nt)
#pragma unroll
                for (int e = 0; e < 4; ++e) accT[mt][nt][e] += accW[mt][nt][e];

        __syncthreads();
    }

#pragma unroll
    for (int mt = 0; mt < 2; ++mt) {
        size_t row = row0 + wm * 32 + mt * 16 + (lane >> 2);
#pragma unroll
        for (int nt = 0; nt < 8; ++nt) {
            int col = wn * 64 + nt * 8 + (lane & 3) * 2;
            *(float2*)&Y[row * HID + col]       = make_float2(accT[mt][nt][0], accT[mt][nt][1]);
            *(float2*)&Y[(row + 8) * HID + col] = make_float2(accT[mt][nt][2], accT[mt][nt][3]);
        }
    }
}

// ---------------- assign on HMMA: sims = E @ Pn^T, in-register argmax -------
// CTA: 128 rows. All 256 protos' hi/mid images (132KB) cp.async'd to smem;
// E tile split on the fly. 8 warps: wm=wid>>1 (32 rows), wn=wid&1 (128 protos,
// processed as 2 chunks of 64). Same fp16x2 4-product + two-stage flush.
__global__ void __launch_bounds__(256, 1) assign_mma_kernel(
    const float* __restrict__ E, const char* __restrict__ Pg,
    float* __restrict__ outA)
{
    extern __shared__ char smem[];
    const uint32_t Pbase = smem_u32(smem);
    const uint32_t Ebase = Pbase + EOFF;
    char* Eb = smem + EOFF;

    const int tid = threadIdx.x;
    const int wid = tid >> 5, lane = tid & 31;
    const int wm = wid >> 1, wn = wid & 1;
    const size_t row0 = (size_t)blockIdx.x * 128;

    // copy proto images (whole Pn, hi|mid)
    for (int i = tid; i < (2 * PIMG) / 16; i += 256)
        cp16(Pbase + i * 16, Pg + i * 16);
    asm volatile("cp.async.commit_group;");

    // split E tile: 128 rows x 128 k, 8 elems/task
#pragma unroll
    for (int it = 0; it < 8; ++it) {
        int t = tid + it * 256;
        int r = t >> 4, blk = t & 15;
        const float4* xp = (const float4*)(E + (row0 + r) * HID + blk * 8);
        float4 x0 = xp[0], x1 = xp[1];
        float v[8] = {x0.x, x0.y, x0.z, x0.w, x1.x, x1.y, x1.z, x1.w};
        store8s(Eb, r * ESTR + blk * 16, EIMG, v);
    }
    asm volatile("cp.async.wait_group 0;");
    __syncthreads();

    const uint32_t aGeo = (wm * 32 + (lane & 15)) * ESTR + (lane >> 4) * 16;
    const uint32_t wRow = (uint32_t)(lane & 15) * PSTR;

    // best per (mt, row-half): rows wm*32 + mt*16 + (lane>>2) + half*8
    float best[2][2]; int bidx[2][2];
#pragma unroll
    for (int mt = 0; mt < 2; ++mt)
#pragma unroll
        for (int hf = 0; hf < 2; ++hf) { best[mt][hf] = -3.0e38f; bidx[mt][hf] = 0; }

#pragma unroll
    for (int pc = 0; pc < 2; ++pc) {
        const int pb = wn * 256 + pc * 128;          // proto base offset in bytes
        float accP[2][8][4];
#pragma unroll
        for (int mt = 0; mt < 2; ++mt)
#pragma unroll
            for (int nt = 0; nt < 8; ++nt)
#pragma unroll
                for (int e = 0; e < 4; ++e) accP[mt][nt][e] = 0.0f;

#pragma unroll
        for (int half = 0; half < 2; ++half) {
            float accW[2][8][4];
#pragma unroll
            for (int mt = 0; mt < 2; ++mt)
#pragma unroll
                for (int nt = 0; nt < 8; ++nt)
#pragma unroll
                    for (int e = 0; e < 4; ++e) accW[mt][nt][e] = 0.0f;
#pragma unroll
            for (int ks2 = 0; ks2 < 4; ++ks2) {
                int ks = half * 4 + ks2;
                uint32_t ah[2][4], am[2][4];
#pragma unroll
                for (int mt = 0; mt < 2; ++mt) {
                    uint32_t a = Ebase + aGeo + mt * (16 * ESTR) + ks * 32;
                    ldm_x4(ah[mt], a);
                    ldm_x4(am[mt], a + EIMG);
                }
#pragma unroll
                for (int g = 0; g < 4; ++g) {
                    uint32_t wh[4], wmr[4];
                    uint32_t a = Pbase + wRow + ks * (16 * PSTR)
                               + pb + (lane >> 4) * 16 + g * 32;
                    ldm_x4t(wh,  a);
                    ldm_x4t(wmr, a + PIMG);
#pragma unroll
                    for (int mt = 0; mt < 2; ++mt) {
                        float* a0 = accW[mt][2 * g];
                        float* a1 = accW[mt][2 * g + 1];
                        mma16816(a0, ah[mt], wh);    mma16816(a1, ah[mt], wh + 2);
                        mma16816(a0, ah[mt], wmr);   mma16816(a1, ah[mt], wmr + 2);
                        mma16816(a0, am[mt], wh);    mma16816(a1, am[mt], wh + 2);
                        mma16816(a0, am[mt], wmr);   mma16816(a1, am[mt], wmr + 2);
                    }
                }
            }
#pragma unroll
            for (int mt = 0; mt < 2; ++mt)
#pragma unroll
                for (int nt = 0; nt < 8; ++nt)
#pragma unroll
                    for (int e = 0; e < 4; ++e) accP[mt][nt][e] += accW[mt][nt][e];
        }

        // argmax update (ascending proto index, strict > keeps lowest)
#pragma unroll
        for (int nt = 0; nt < 8; ++nt)
#pragma unroll
            for (int e = 0; e < 4; ++e) {
                int hf = e >> 1;
                int idx = wn * 128 + pc * 64 + nt * 8 + (lane & 3) * 2 + (e & 1);
#pragma unroll
                for (int mt = 0; mt < 2; ++mt)
                    if (accP[mt][nt][e] > best[mt][hf]) {
                        best[mt][hf] = accP[mt][nt][e];
                        bidx[mt][hf] = idx;
                    }
            }
    }

    // reduce across the 4 lanes sharing each row (lane&3 varies), then across
    // the two warps (wn) via smem; lowest-index wins ties.
#pragma unroll
    for (int o = 1; o < 4; o <<= 1)
#pragma unroll
        for (int mt = 0; mt < 2; ++mt)
#pragma unroll
            for (int hf = 0; hf < 2; ++hf) {
                float ov = __shfl_xor_sync(0xffffffffu, best[mt][hf], o);
                int   oi = __shfl_xor_sync(0xffffffffu, bidx[mt][hf], o);
                if (ov > best[mt][hf] || (ov == best[mt][hf] && oi < bidx[mt][hf])) {
                    best[mt][hf] = ov; bidx[mt][hf] = oi;
                }
            }
    __syncthreads();                    // smem (E area) reusable for reduction
    float* sVal = (float*)smem;         // [128] per wn: 2 planes of 128 rows
    int*   sIdx = (int*)(smem + 2 * 128 * 4);
    if ((lane & 3) == 0) {
#pragma unroll
        for (int mt = 0; mt < 2; ++mt)
#pragma unroll
            for (int hf = 0; hf < 2; ++hf) {
                int r = wm * 32 + mt * 16 + (lane >> 2) + hf * 8;
                sVal[wn * 128 + r] = best[mt][hf];
                sIdx[wn * 128 + r] = bidx[mt][hf];
            }
    }
    __syncthreads();
    if (tid < 128) {
        float v0 = sVal[tid], v1 = sVal[128 + tid];
        int   i0 = sIdx[tid], i1 = sIdx[128 + tid];
        int bi = (v1 > v0 || (v1 == v0 && i1 < i0)) ? i1 : i0;
        outA[row0 + tid] = (float)bi;
    }
}

// ---------------- launch ----------------------------------------------------
extern "C" void kernel_launch(void* const* d_in, const int* in_sizes, int n_in,
                              void* d_out, int out_size)
{
    const float* x    = (const float*)d_in[0];
    const float* prot = (const float*)d_in[1];
    const float* grid = (const float*)d_in[2];
    const float* bw1  = (const float*)d_in[3];
    const float* sw1  = (const float*)d_in[4];
    const float* sc1  = (const float*)d_in[5];
    const float* bw2  = (const float*)d_in[6];
    const float* sw2  = (const float*)d_in[7];
    const float* sc2  = (const float*)d_in[8];
    float* out = (float*)d_out;

    const int N  = in_sizes[0] / HID;
    const int Kp = in_sizes[1] / HID;   // 256

    uint4 *W1, *W2, *ps; float *h;
    cudaGetSymbolAddress((void**)&W1, g_W1);
    cudaGetSymbolAddress((void**)&W2, g_W2);
    cudaGetSymbolAddress((void**)&h,  g_h);
    cudaGetSymbolAddress((void**)&ps, g_ps);

    cudaFuncSetAttribute(layer_mma_kernel,  cudaFuncAttributeMaxDynamicSharedMemorySize, SMEM_LAYER);
    cudaFuncSetAttribute(assign_mma_kernel, cudaFuncAttributeMaxDynamicSharedMemorySize, SMEM_ASSIGN);

    const int wtasks = NCH * 64 * HID;
    prep_w_kernel<<<(wtasks + 255) / 256, 256>>>(bw1, sw1, sc1, (char*)W1);
    prep_w_kernel<<<(wtasks + 255) / 256, 256>>>(bw2, sw2, sc2, (char*)W2);
    prep_p_kernel<<<Kp, HID>>>(prot, (char*)ps);

    layer_mma_kernel<<<N / BM, 256, SMEM_LAYER>>>(x, (const char*)W1, grid, h);
    layer_mma_kernel<<<N / BM, 256, SMEM_LAYER>>>(h, (const char*)W2, grid, out);

    if ((size_t)out_size >= (size_t)N * HID + (size_t)N)
        assign_mma_kernel<<<N / 128, 256, SMEM_ASSIGN>>>(out, (const char*)ps,
                                                         out + (size_t)N * HID);
}

// round 14
// speedup vs baseline: 2.3889x; 1.1374x over previous
#include <cuda_runtime.h>
#include <cuda_fp16.h>
#include <math.h>
#include <cstdint>

#define HID   128
#define NCH   18                 // 2 silu chunks + 16 spline chunks, 64 k each
#define BM    64                 // rows per CTA (half-size tile -> 2 CTAs/SM)
#define NMAX  131072
#define KPMAX 256

#define ASTR  144                // A row stride bytes (64 k * 2B + 16B pad)
#define ATILE (BM * ASTR)        // 9216 (one image)
#define ABUF  (2 * ATILE)        // 18432: hi | mid
#define WSTR  272                // W k-row stride bytes (128 o * 2B + 16B pad)
#define WIMG  17408              // 64 * 272 (one image)
#define WBLOB (2 * WIMG)         // 34816: hi | mid
#define WOFF  (2 * ABUF)         // 36864
#define SMEM_LAYER (WOFF + 2 * WBLOB)   // 106496 (x2 CTAs = 208KB <= 228KB/SM)

// assign kernel layout
#define PSTR  528                // proto k-row stride (256 protos * 2B + 16 pad)
#define PIMG  67584              // 128 * 528 (one image)
#define ESTR  272                // E row stride (128 k * 2B + 16 pad)
#define EIMG  34816              // 128 * 272
#define EOFF  (2 * PIMG)         // 135168
#define SMEM_ASSIGN (EOFF + 2 * EIMG)   // 204800

// ---------------- scratch (device globals; no allocation allowed) ----------
__device__ uint4 g_W1[(NCH * WBLOB) / 16];
__device__ uint4 g_W2[(NCH * WBLOB) / 16];
__device__ float g_h[(size_t)NMAX * HID];
__device__ uint4 g_ps[(2 * PIMG) / 16];   // pre-split normalized protos (hi|mid)

// ---------------- PTX helpers (sm_80-portable; no tcgen05) ------------------
__device__ __forceinline__ uint32_t smem_u32(const void* p) {
    uint32_t a;
    asm("{ .reg .u64 t; cvta.to.shared.u64 t, %1; cvt.u32.u64 %0, t; }" : "=r"(a) : "l"(p));
    return a;
}
__device__ __forceinline__ void ldm_x4(uint32_t* r, uint32_t a) {
    asm volatile("ldmatrix.sync.aligned.m8n8.x4.shared.b16 {%0,%1,%2,%3}, [%4];"
        : "=r"(r[0]), "=r"(r[1]), "=r"(r[2]), "=r"(r[3]) : "r"(a));
}
__device__ __forceinline__ void ldm_x4t(uint32_t* r, uint32_t a) {
    asm volatile("ldmatrix.sync.aligned.m8n8.x4.trans.shared.b16 {%0,%1,%2,%3}, [%4];"
        : "=r"(r[0]), "=r"(r[1]), "=r"(r[2]), "=r"(r[3]) : "r"(a));
}
// fp16 inputs, fp32 accumulator (11-bit mantissa => 2-way split reaches 2^-22)
__device__ __forceinline__ void mma16816(float* d, const uint32_t* a, const uint32_t* b) {
    asm volatile("mma.sync.aligned.m16n8k16.row.col.f32.f16.f16.f32 "
        "{%0,%1,%2,%3}, {%4,%5,%6,%7}, {%8,%9}, {%0,%1,%2,%3};"
        : "+f"(d[0]), "+f"(d[1]), "+f"(d[2]), "+f"(d[3])
        : "r"(a[0]), "r"(a[1]), "r"(a[2]), "r"(a[3]), "r"(b[0]), "r"(b[1]));
}
__device__ __forceinline__ void cp16(uint32_t saddr, const void* gaddr) {
    asm volatile("cp.async.cg.shared.global [%0], [%1], 16;" :: "r"(saddr), "l"(gaddr));
}

// ---------------- 2-way fp16 split (eps ~ 2^-22) ----------------------------
__device__ __forceinline__ void split2(float a, __half& h, __half& m) {
    h = __float2half_rn(a);
    m = __float2half_rn(a - __half2float(h));
}

// ---------------- weight prep: k-major fp16 hi/mid images -------------------
__global__ void prep_w_kernel(const float* __restrict__ bw,
                              const float* __restrict__ sw,
                              const float* __restrict__ sc,
                              char* __restrict__ Wout)
{
    int idx = blockIdx.x * 256 + threadIdx.x;      // (chunk, k, o)
    if (idx >= NCH * 64 * HID) return;
    int chunk = idx / (64 * HID);
    int rem   = idx - chunk * (64 * HID);
    int k = rem >> 7, o = rem & 127;
    float w;
    if (chunk < 2) {
        w = bw[o * HID + chunk * 64 + k];
    } else {
        int f = (chunk - 2) * 8 + (k >> 3);
        w = sw[(o * HID + f) * 8 + (k & 7)] * sc[o * HID + f];
    }
    __half h, m;
    split2(w, h, m);
    char* base = Wout + (size_t)chunk * WBLOB + k * WSTR + o * 2;
    *(__half*)(base)        = h;
    *(__half*)(base + WIMG) = m;
}

// ---------------- prototype prep: normalize + split to k-major images -------
__global__ void prep_p_kernel(const float* __restrict__ P, char* __restrict__ Pout)
{
    int r = blockIdx.x, t = threadIdx.x;           // r = proto, t = k
    float v = P[r * HID + t];
    float s = v * v;
#pragma unroll
    for (int o = 16; o > 0; o >>= 1) s += __shfl_xor_sync(0xffffffffu, s, o);
    __shared__ float red[4];
    if ((t & 31) == 0) red[t >> 5] = s;
    __syncthreads();
    float nrm = fmaxf(sqrtf(red[0] + red[1] + red[2] + red[3]), 1e-8f);
    __half h, m;
    split2(v / nrm, h, m);
    char* base = Pout + t * PSTR + r * 2;
    *(__half*)(base)        = h;
    *(__half*)(base + PIMG) = m;
}

// ---------------- A pack: 8 values -> fp16 hi/mid, 16B stores ---------------
__device__ __forceinline__ void store8s(char* Ab, uint32_t off, int img_stride,
                                        const float* v)
{
    __half h[8], m[8];
#pragma unroll
    for (int e = 0; e < 8; ++e) split2(v[e], h[e], m[e]);
    *(uint4*)(Ab + off)              = *(uint4*)h;
    *(uint4*)(Ab + img_stride + off) = *(uint4*)m;
}

// ---------------- A-chunk generation (reads x from gmem/L2) -----------------
__device__ __forceinline__ void gen_chunk(int cc, char* Ab, const float* __restrict__ X,
                                          size_t row0, int tid, float g0, float invh)
{
    if (cc < 2) {
#pragma unroll
        for (int it = 0; it < 2; ++it) {           // 64 rows x 8 blks = 512 tasks
            int t = tid + it * 256;
            int r = t >> 3, blk = t & 7;
            const float4* xp = (const float4*)(X + (row0 + r) * HID + cc * 64 + blk * 8);
            float4 x0 = xp[0], x1 = xp[1];
            float v[8] = {x0.x, x0.y, x0.z, x0.w, x1.x, x1.y, x1.z, x1.w};
#pragma unroll
            for (int e = 0; e < 8; ++e) {
                float x = v[e];
                v[e] = x / (1.0f + __expf(-x));
            }
            store8s(Ab, r * ASTR + blk * 16, ATILE, v);
        }
    } else {
        const int f0 = (cc - 2) * 8;
#pragma unroll
        for (int it = 0; it < 2; ++it) {           // 64 rows x 8 features
            int t = tid + it * 256;
            int r = t >> 3, fl = t & 7;
            float x = X[(row0 + r) * HID + f0 + fl];
            float tt = (x - g0) * invh;              // uniform-grid cubic B-spline
            float fi = floorf(tt);
            int   i  = (int)fi;
            float u  = tt - fi;
            float u2 = u * u, u3 = u2 * u, om = 1.0f - u;
            float c0v = u3 * (1.0f / 6.0f);
            float c1v = (1.0f / 6.0f) * (1.0f + 3.0f * u + 3.0f * u2 - 3.0f * u3);
            float c2v = (1.0f / 6.0f) * (4.0f - 6.0f * u2 + 3.0f * u3);
            float c3v = om * om * om * (1.0f / 6.0f);
            float v[8];
#pragma unroll
            for (int j = 0; j < 8; ++j) {
                int mm_ = i - j;
                float val = 0.0f;
                val = (mm_ == 0) ? c0v : val;
                val = (mm_ == 1) ? c1v : val;
                val = (mm_ == 2) ? c2v : val;
                val = (mm_ == 3) ? c3v : val;
                v[j] = val;
            }
            store8s(Ab, r * ASTR + fl * 16, ATILE, v);
        }
    }
}

// ---------------- fused KAN layer on HMMA (fp16x2, 4 products) --------------
// CTA: 64 rows x 128 outs, 8 warps: wm=wid>>1 (16 rows), wn=wid&1 (64 cols).
// 2 CTAs/SM: co-resident CTA covers the gen/flush/barrier bubbles.
__global__ void __launch_bounds__(256, 2) layer_mma_kernel(
    const float* __restrict__ X, const char* __restrict__ Wg,
    const float* __restrict__ grid, float* __restrict__ Y)
{
    extern __shared__ char smem[];
    const uint32_t Abase = smem_u32(smem);
    const uint32_t Wbase = Abase + WOFF;

    const int tid = threadIdx.x;
    const int wid = tid >> 5, lane = tid & 31;
    const int wm = wid >> 1, wn = wid & 1;
    const size_t row0 = (size_t)blockIdx.x * BM;

    const float g0   = grid[0];
    const float invh = 1.0f / (grid[1] - grid[0]);

    gen_chunk(0, smem, X, row0, tid, g0, invh);
    for (int i = tid; i < WBLOB / 16; i += 256)
        cp16(Wbase + i * 16, Wg + i * 16);
    asm volatile("cp.async.commit_group;");

    float accT[8][4];
#pragma unroll
    for (int nt = 0; nt < 8; ++nt)
#pragma unroll
        for (int e = 0; e < 4; ++e) accT[nt][e] = 0.0f;

    const uint32_t aGeo = (wm * 16 + (lane & 15)) * ASTR + (lane >> 4) * 16;
    const uint32_t wCol = wn * 128 + (lane >> 4) * 16;
    const uint32_t wRow = (uint32_t)(lane & 15) * WSTR;

    for (int c = 0; c < NCH; ++c) {
        const int b = c & 1;

        if (c + 1 < NCH) {
            const char* src = Wg + (size_t)(c + 1) * WBLOB;
            uint32_t dst = Wbase + (b ^ 1) * WBLOB;
            for (int i = tid; i < WBLOB / 16; i += 256)
                cp16(dst + i * 16, src + i * 16);
            asm volatile("cp.async.commit_group;");
            asm volatile("cp.async.wait_group 1;");
        } else {
            asm volatile("cp.async.wait_group 0;");
        }
        __syncthreads();   // ALL threads' W(c) copies complete; A(c) visible

        float accW[8][4];
#pragma unroll
        for (int nt = 0; nt < 8; ++nt)
#pragma unroll
            for (int e = 0; e < 4; ++e) accW[nt][e] = 0.0f;

        const uint32_t Ab_ = Abase + b * ABUF;
        const uint32_t Wb  = Wbase + b * WBLOB;
#pragma unroll
        for (int ks = 0; ks < 4; ++ks) {
            uint32_t ah[4], am[4];
            {
                uint32_t a = Ab_ + aGeo + ks * 32;
                ldm_x4(ah, a);
                ldm_x4(am, a + ATILE);
            }
#pragma unroll
            for (int g = 0; g < 4; ++g) {
                uint32_t wh[4], wmr[4];
                uint32_t a = Wb + wRow + ks * (16 * WSTR) + wCol + g * 32;
                ldm_x4t(wh,  a);
                ldm_x4t(wmr, a + WIMG);
                float* a0 = accW[2 * g];
                float* a1 = accW[2 * g + 1];
                mma16816(a0, ah, wh);       mma16816(a1, ah, wh + 2);
                mma16816(a0, ah, wmr);      mma16816(a1, ah, wmr + 2);
                mma16816(a0, am, wh);       mma16816(a1, am, wh + 2);
                mma16816(a0, am, wmr);      mma16816(a1, am, wmr + 2);
            }
        }

        if (c + 1 < NCH)
            gen_chunk(c + 1, smem + (b ^ 1) * ABUF, X, row0, tid, g0, invh);

#pragma unroll
        for (int nt = 0; nt < 8; ++nt)
#pragma unroll
            for (int e = 0; e < 4; ++e) accT[nt][e] += accW[nt][e];

        __syncthreads();
    }

    // epilogue: fragment -> gmem
    {
        size_t row = row0 + wm * 16 + (lane >> 2);
#pragma unroll
        for (int nt = 0; nt < 8; ++nt) {
            int col = wn * 64 + nt * 8 + (lane & 3) * 2;
            *(float2*)&Y[row * HID + col]       = make_float2(accT[nt][0], accT[nt][1]);
            *(float2*)&Y[(row + 8) * HID + col] = make_float2(accT[nt][2], accT[nt][3]);
        }
    }
}

// ---------------- assign on HMMA: sims = E @ Pn^T, in-register argmax -------
__global__ void __launch_bounds__(256, 1) assign_mma_kernel(
    const float* __restrict__ E, const char* __restrict__ Pg,
    float* __restrict__ outA)
{
    extern __shared__ char smem[];
    const uint32_t Pbase = smem_u32(smem);
    const uint32_t Ebase = Pbase + EOFF;
    char* Eb = smem + EOFF;

    const int tid = threadIdx.x;
    const int wid = tid >> 5, lane = tid & 31;
    const int wm = wid >> 1, wn = wid & 1;
    const size_t row0 = (size_t)blockIdx.x * 128;

    for (int i = tid; i < (2 * PIMG) / 16; i += 256)
        cp16(Pbase + i * 16, Pg + i * 16);
    asm volatile("cp.async.commit_group;");

#pragma unroll
    for (int it = 0; it < 8; ++it) {
        int t = tid + it * 256;
        int r = t >> 4, blk = t & 15;
        const float4* xp = (const float4*)(E + (row0 + r) * HID + blk * 8);
        float4 x0 = xp[0], x1 = xp[1];
        float v[8] = {x0.x, x0.y, x0.z, x0.w, x1.x, x1.y, x1.z, x1.w};
        store8s(Eb, r * ESTR + blk * 16, EIMG, v);
    }
    asm volatile("cp.async.wait_group 0;");
    __syncthreads();

    const uint32_t aGeo = (wm * 32 + (lane & 15)) * ESTR + (lane >> 4) * 16;
    const uint32_t wRow = (uint32_t)(lane & 15) * PSTR;

    float best[2][2]; int bidx[2][2];
#pragma unroll
    for (int mt = 0; mt < 2; ++mt)
#pragma unroll
        for (int hf = 0; hf < 2; ++hf) { best[mt][hf] = -3.0e38f; bidx[mt][hf] = 0; }

#pragma unroll
    for (int pc = 0; pc < 2; ++pc) {
        const int pb = wn * 256 + pc * 128;
        float accP[2][8][4];
#pragma unroll
        for (int mt = 0; mt < 2; ++mt)
#pragma unroll
            for (int nt = 0; nt < 8; ++nt)
#pragma unroll
                for (int e = 0; e < 4; ++e) accP[mt][nt][e] = 0.0f;

#pragma unroll
        for (int half = 0; half < 2; ++half) {
            float accW[2][8][4];
#pragma unroll
            for (int mt = 0; mt < 2; ++mt)
#pragma unroll
                for (int nt = 0; nt < 8; ++nt)
#pragma unroll
                    for (int e = 0; e < 4; ++e) accW[mt][nt][e] = 0.0f;
#pragma unroll
            for (int ks2 = 0; ks2 < 4; ++ks2) {
                int ks = half * 4 + ks2;
                uint32_t ah[2][4], am[2][4];
#pragma unroll
                for (int mt = 0; mt < 2; ++mt) {
                    uint32_t a = Ebase + aGeo + mt * (16 * ESTR) + ks * 32;
                    ldm_x4(ah[mt], a);
                    ldm_x4(am[mt], a + EIMG);
                }
#pragma unroll
                for (int g = 0; g < 4; ++g) {
                    uint32_t wh[4], wmr[4];
                    uint32_t a = Pbase + wRow + ks * (16 * PSTR)
                               + pb + (lane >> 4) * 16 + g * 32;
                    ldm_x4t(wh,  a);
                    ldm_x4t(wmr, a + PIMG);
#pragma unroll
                    for (int mt = 0; mt < 2; ++mt) {
                        float* a0 = accW[mt][2 * g];
                        float* a1 = accW[mt][2 * g + 1];
                        mma16816(a0, ah[mt], wh);    mma16816(a1, ah[mt], wh + 2);
                        mma16816(a0, ah[mt], wmr);   mma16816(a1, ah[mt], wmr + 2);
                        mma16816(a0, am[mt], wh);    mma16816(a1, am[mt], wh + 2);
                        mma16816(a0, am[mt], wmr);   mma16816(a1, am[mt], wmr + 2);
                    }
                }
            }
#pragma unroll
            for (int mt = 0; mt < 2; ++mt)
#pragma unroll
                for (int nt = 0; nt < 8; ++nt)
#pragma unroll
                    for (int e = 0; e < 4; ++e) accP[mt][nt][e] += accW[mt][nt][e];
        }

#pragma unroll
        for (int nt = 0; nt < 8; ++nt)
#pragma unroll
            for (int e = 0; e < 4; ++e) {
                int hf = e >> 1;
                int idx = wn * 128 + pc * 64 + nt * 8 + (lane & 3) * 2 + (e & 1);
#pragma unroll
                for (int mt = 0; mt < 2; ++mt)
                    if (accP[mt][nt][e] > best[mt][hf]) {
                        best[mt][hf] = accP[mt][nt][e];
                        bidx[mt][hf] = idx;
                    }
            }
    }

#pragma unroll
    for (int o = 1; o < 4; o <<= 1)
#pragma unroll
        for (int mt = 0; mt < 2; ++mt)
#pragma unroll
            for (int hf = 0; hf < 2; ++hf) {
                float ov = __shfl_xor_sync(0xffffffffu, best[mt][hf], o);
                int   oi = __shfl_xor_sync(0xffffffffu, bidx[mt][hf], o);
                if (ov > best[mt][hf] || (ov == best[mt][hf] && oi < bidx[mt][hf])) {
                    best[mt][hf] = ov; bidx[mt][hf] = oi;
                }
            }
    __syncthreads();
    float* sVal = (float*)smem;
    int*   sIdx = (int*)(smem + 2 * 128 * 4);
    if ((lane & 3) == 0) {
#pragma unroll
        for (int mt = 0; mt < 2; ++mt)
#pragma unroll
            for (int hf = 0; hf < 2; ++hf) {
                int r = wm * 32 + mt * 16 + (lane >> 2) + hf * 8;
                sVal[wn * 128 + r] = best[mt][hf];
                sIdx[wn * 128 + r] = bidx[mt][hf];
            }
    }
    __syncthreads();
    if (tid < 128) {
        float v0 = sVal[tid], v1 = sVal[128 + tid];
        int   i0 = sIdx[tid], i1 = sIdx[128 + tid];
        int bi = (v1 > v0 || (v1 == v0 && i1 < i0)) ? i1 : i0;
        outA[row0 + tid] = (float)bi;
    }
}

// ---------------- launch ----------------------------------------------------
extern "C" void kernel_launch(void* const* d_in, const int* in_sizes, int n_in,
                              void* d_out, int out_size)
{
    const float* x    = (const float*)d_in[0];
    const float* prot = (const float*)d_in[1];
    const float* grid = (const float*)d_in[2];
    const float* bw1  = (const float*)d_in[3];
    const float* sw1  = (const float*)d_in[4];
    const float* sc1  = (const float*)d_in[5];
    const float* bw2  = (const float*)d_in[6];
    const float* sw2  = (const float*)d_in[7];
    const float* sc2  = (const float*)d_in[8];
    float* out = (float*)d_out;

    const int N  = in_sizes[0] / HID;
    const int Kp = in_sizes[1] / HID;   // 256

    uint4 *W1, *W2, *ps; float *h;
    cudaGetSymbolAddress((void**)&W1, g_W1);
    cudaGetSymbolAddress((void**)&W2, g_W2);
    cudaGetSymbolAddress((void**)&h,  g_h);
    cudaGetSymbolAddress((void**)&ps, g_ps);

    cudaFuncSetAttribute(layer_mma_kernel,  cudaFuncAttributeMaxDynamicSharedMemorySize, SMEM_LAYER);
    cudaFuncSetAttribute(assign_mma_kernel, cudaFuncAttributeMaxDynamicSharedMemorySize, SMEM_ASSIGN);

    const int wtasks = NCH * 64 * HID;
    prep_w_kernel<<<(wtasks + 255) / 256, 256>>>(bw1, sw1, sc1, (char*)W1);
    prep_w_kernel<<<(wtasks + 255) / 256, 256>>>(bw2, sw2, sc2, (char*)W2);
    prep_p_kernel<<<Kp, HID>>>(prot, (char*)ps);

    layer_mma_kernel<<<N / BM, 256, SMEM_LAYER>>>(x, (const char*)W1, grid, h);
    layer_mma_kernel<<<N / BM, 256, SMEM_LAYER>>>(h, (const char*)W2, grid, out);

    if ((size_t)out_size >= (size_t)N * HID + (size_t)N)
        assign_mma_kernel<<<N / 128, 256, SMEM_ASSIGN>>>(out, (const char*)ps,
                                                         out + (size_t)N * HID);
}

// round 15
// speedup vs baseline: 2.8217x; 1.1812x over previous
#include <cuda_runtime.h>
#include <cuda_fp16.h>
#include <math.h>
#include <cstdint>

#define HID   128
#define NCH   18                 // 2 silu chunks + 16 spline chunks, 64 k each
#define BM    64                 // rows per CTA (half-size tile -> 2 CTAs/SM)
#define NMAX  131072
#define KPMAX 256

#define ASTR  144                // A row stride bytes (64 k * 2B + 16B pad)
#define ATILE (BM * ASTR)        // 9216 (one image)
#define ABUF  (2 * ATILE)        // 18432: hi | mid
#define WSTR  272                // W k-row stride bytes (128 o * 2B + 16B pad)
#define WIMG  17408              // 64 * 272 (one image)
#define WBLOB (2 * WIMG)         // 34816: hi | mid
#define WOFF  (2 * ABUF)         // 36864
#define SMEM_LAYER (WOFF + 2 * WBLOB)   // 106496 (x2 CTAs = 208KB <= 228KB/SM)

// assign kernel layout
#define PSTR  528                // proto k-row stride (256 protos * 2B + 16 pad)
#define PIMG  67584              // 128 * 528 (one image)
#define ESTR  272                // E row stride (128 k * 2B + 16 pad)
#define EIMG  34816              // 128 * 272
#define EOFF  (2 * PIMG)         // 135168
#define SMEM_ASSIGN (EOFF + 2 * EIMG)   // 204800

// ---------------- scratch (device globals; no allocation allowed) ----------
__device__ uint4 g_W1[(NCH * WBLOB) / 16];
__device__ uint4 g_W2[(NCH * WBLOB) / 16];
__device__ float g_h[(size_t)NMAX * HID];
__device__ uint4 g_ps[(2 * PIMG) / 16];   // pre-split normalized protos (hi|mid)

// ---------------- PTX helpers (sm_80-portable; no tcgen05) ------------------
__device__ __forceinline__ uint32_t smem_u32(const void* p) {
    uint32_t a;
    asm("{ .reg .u64 t; cvta.to.shared.u64 t, %1; cvt.u32.u64 %0, t; }" : "=r"(a) : "l"(p));
    return a;
}
__device__ __forceinline__ void ldm_x4(uint32_t* r, uint32_t a) {
    asm volatile("ldmatrix.sync.aligned.m8n8.x4.shared.b16 {%0,%1,%2,%3}, [%4];"
        : "=r"(r[0]), "=r"(r[1]), "=r"(r[2]), "=r"(r[3]) : "r"(a));
}
__device__ __forceinline__ void ldm_x4t(uint32_t* r, uint32_t a) {
    asm volatile("ldmatrix.sync.aligned.m8n8.x4.trans.shared.b16 {%0,%1,%2,%3}, [%4];"
        : "=r"(r[0]), "=r"(r[1]), "=r"(r[2]), "=r"(r[3]) : "r"(a));
}
// fp16 inputs, fp32 accumulator. fp16 split: h 11 bits, m next 11, eps~2^-22.
// Products hh+hm+mh suffice: the mm term is ~2^-24, BELOW the split floor.
__device__ __forceinline__ void mma16816(float* d, const uint32_t* a, const uint32_t* b) {
    asm volatile("mma.sync.aligned.m16n8k16.row.col.f32.f16.f16.f32 "
        "{%0,%1,%2,%3}, {%4,%5,%6,%7}, {%8,%9}, {%0,%1,%2,%3};"
        : "+f"(d[0]), "+f"(d[1]), "+f"(d[2]), "+f"(d[3])
        : "r"(a[0]), "r"(a[1]), "r"(a[2]), "r"(a[3]), "r"(b[0]), "r"(b[1]));
}
__device__ __forceinline__ void cp16(uint32_t saddr, const void* gaddr) {
    asm volatile("cp.async.cg.shared.global [%0], [%1], 16;" :: "r"(saddr), "l"(gaddr));
}

// ---------------- 2-way fp16 split (eps ~ 2^-22) ----------------------------
__device__ __forceinline__ void split2(float a, __half& h, __half& m) {
    h = __float2half_rn(a);
    m = __float2half_rn(a - __half2float(h));
}

// ---------------- weight prep: k-major fp16 hi/mid images -------------------
__global__ void prep_w_kernel(const float* __restrict__ bw,
                              const float* __restrict__ sw,
                              const float* __restrict__ sc,
                              char* __restrict__ Wout)
{
    int idx = blockIdx.x * 256 + threadIdx.x;      // (chunk, k, o)
    if (idx >= NCH * 64 * HID) return;
    int chunk = idx / (64 * HID);
    int rem   = idx - chunk * (64 * HID);
    int k = rem >> 7, o = rem & 127;
    float w;
    if (chunk < 2) {
        w = bw[o * HID + chunk * 64 + k];
    } else {
        int f = (chunk - 2) * 8 + (k >> 3);
        w = sw[(o * HID + f) * 8 + (k & 7)] * sc[o * HID + f];
    }
    __half h, m;
    split2(w, h, m);
    char* base = Wout + (size_t)chunk * WBLOB + k * WSTR + o * 2;
    *(__half*)(base)        = h;
    *(__half*)(base + WIMG) = m;
}

// ---------------- prototype prep: normalize + split to k-major images -------
__global__ void prep_p_kernel(const float* __restrict__ P, char* __restrict__ Pout)
{
    int r = blockIdx.x, t = threadIdx.x;           // r = proto, t = k
    float v = P[r * HID + t];
    float s = v * v;
#pragma unroll
    for (int o = 16; o > 0; o >>= 1) s += __shfl_xor_sync(0xffffffffu, s, o);
    __shared__ float red[4];
    if ((t & 31) == 0) red[t >> 5] = s;
    __syncthreads();
    float nrm = fmaxf(sqrtf(red[0] + red[1] + red[2] + red[3]), 1e-8f);
    __half h, m;
    split2(v / nrm, h, m);
    char* base = Pout + t * PSTR + r * 2;
    *(__half*)(base)        = h;
    *(__half*)(base + PIMG) = m;
}

// ---------------- A pack: 8 values -> fp16 hi/mid, 16B stores ---------------
__device__ __forceinline__ void store8s(char* Ab, uint32_t off, int img_stride,
                                        const float* v)
{
    __half h[8], m[8];
#pragma unroll
    for (int e = 0; e < 8; ++e) split2(v[e], h[e], m[e]);
    *(uint4*)(Ab + off)              = *(uint4*)h;
    *(uint4*)(Ab + img_stride + off) = *(uint4*)m;
}

// ---------------- A-chunk generation (reads x from gmem/L2) -----------------
__device__ __forceinline__ void gen_chunk(int cc, char* Ab, const float* __restrict__ X,
                                          size_t row0, int tid, float g0, float invh)
{
    if (cc < 2) {
#pragma unroll
        for (int it = 0; it < 2; ++it) {           // 64 rows x 8 blks = 512 tasks
            int t = tid + it * 256;
            int r = t >> 3, blk = t & 7;
            const float4* xp = (const float4*)(X + (row0 + r) * HID + cc * 64 + blk * 8);
            float4 x0 = xp[0], x1 = xp[1];
            float v[8] = {x0.x, x0.y, x0.z, x0.w, x1.x, x1.y, x1.z, x1.w};
#pragma unroll
            for (int e = 0; e < 8; ++e) {
                float x = v[e];
                v[e] = x / (1.0f + __expf(-x));
            }
            store8s(Ab, r * ASTR + blk * 16, ATILE, v);
        }
    } else {
        const int f0 = (cc - 2) * 8;
#pragma unroll
        for (int it = 0; it < 2; ++it) {           // 64 rows x 8 features
            int t = tid + it * 256;
            int r = t >> 3, fl = t & 7;
            float x = X[(row0 + r) * HID + f0 + fl];
            float tt = (x - g0) * invh;              // uniform-grid cubic B-spline
            float fi = floorf(tt);
            int   i  = (int)fi;
            float u  = tt - fi;
            float u2 = u * u, u3 = u2 * u, om = 1.0f - u;
            float c0v = u3 * (1.0f / 6.0f);
            float c1v = (1.0f / 6.0f) * (1.0f + 3.0f * u + 3.0f * u2 - 3.0f * u3);
            float c2v = (1.0f / 6.0f) * (4.0f - 6.0f * u2 + 3.0f * u3);
            float c3v = om * om * om * (1.0f / 6.0f);
            float v[8];
#pragma unroll
            for (int j = 0; j < 8; ++j) {
                int mm_ = i - j;
                float val = 0.0f;
                val = (mm_ == 0) ? c0v : val;
                val = (mm_ == 1) ? c1v : val;
                val = (mm_ == 2) ? c2v : val;
                val = (mm_ == 3) ? c3v : val;
                v[j] = val;
            }
            store8s(Ab, r * ASTR + fl * 16, ATILE, v);
        }
    }
}

// ---------------- fused KAN layer on HMMA (fp16x2, 3 products) --------------
// CTA: 64 rows x 128 outs, 8 warps: wm=wid>>1 (16 rows), wn=wid&1 (64 cols).
// 2 CTAs/SM. D_chunk = Ah*Wh + Ah*Wm + Am*Wh (mm ~2^-24, below split floor).
__global__ void __launch_bounds__(256, 2) layer_mma_kernel(
    const float* __restrict__ X, const char* __restrict__ Wg,
    const float* __restrict__ grid, float* __restrict__ Y)
{
    extern __shared__ char smem[];
    const uint32_t Abase = smem_u32(smem);
    const uint32_t Wbase = Abase + WOFF;

    const int tid = threadIdx.x;
    const int wid = tid >> 5, lane = tid & 31;
    const int wm = wid >> 1, wn = wid & 1;
    const size_t row0 = (size_t)blockIdx.x * BM;

    const float g0   = grid[0];
    const float invh = 1.0f / (grid[1] - grid[0]);

    gen_chunk(0, smem, X, row0, tid, g0, invh);
    for (int i = tid; i < WBLOB / 16; i += 256)
        cp16(Wbase + i * 16, Wg + i * 16);
    asm volatile("cp.async.commit_group;");

    float accT[8][4];
#pragma unroll
    for (int nt = 0; nt < 8; ++nt)
#pragma unroll
        for (int e = 0; e < 4; ++e) accT[nt][e] = 0.0f;

    const uint32_t aGeo = (wm * 16 + (lane & 15)) * ASTR + (lane >> 4) * 16;
    const uint32_t wCol = wn * 128 + (lane >> 4) * 16;
    const uint32_t wRow = (uint32_t)(lane & 15) * WSTR;

    for (int c = 0; c < NCH; ++c) {
        const int b = c & 1;

        if (c + 1 < NCH) {
            const char* src = Wg + (size_t)(c + 1) * WBLOB;
            uint32_t dst = Wbase + (b ^ 1) * WBLOB;
            for (int i = tid; i < WBLOB / 16; i += 256)
                cp16(dst + i * 16, src + i * 16);
            asm volatile("cp.async.commit_group;");
            asm volatile("cp.async.wait_group 1;");
        } else {
            asm volatile("cp.async.wait_group 0;");
        }
        __syncthreads();   // ALL threads' W(c) copies complete; A(c) visible

        float accW[8][4];
#pragma unroll
        for (int nt = 0; nt < 8; ++nt)
#pragma unroll
            for (int e = 0; e < 4; ++e) accW[nt][e] = 0.0f;

        const uint32_t Ab_ = Abase + b * ABUF;
        const uint32_t Wb  = Wbase + b * WBLOB;
#pragma unroll
        for (int ks = 0; ks < 4; ++ks) {
            uint32_t ah[4], am[4];
            {
                uint32_t a = Ab_ + aGeo + ks * 32;
                ldm_x4(ah, a);
                ldm_x4(am, a + ATILE);
            }
#pragma unroll
            for (int g = 0; g < 4; ++g) {
                uint32_t wh[4], wmr[4];
                uint32_t a = Wb + wRow + ks * (16 * WSTR) + wCol + g * 32;
                ldm_x4t(wh,  a);
                ldm_x4t(wmr, a + WIMG);
                float* a0 = accW[2 * g];
                float* a1 = accW[2 * g + 1];
                mma16816(a0, ah, wh);       mma16816(a1, ah, wh + 2);
                mma16816(a0, ah, wmr);      mma16816(a1, ah, wmr + 2);
                mma16816(a0, am, wh);       mma16816(a1, am, wh + 2);
            }
        }

        if (c + 1 < NCH)
            gen_chunk(c + 1, smem + (b ^ 1) * ABUF, X, row0, tid, g0, invh);

#pragma unroll
        for (int nt = 0; nt < 8; ++nt)
#pragma unroll
            for (int e = 0; e < 4; ++e) accT[nt][e] += accW[nt][e];

        __syncthreads();
    }

    // epilogue: fragment -> gmem
    {
        size_t row = row0 + wm * 16 + (lane >> 2);
#pragma unroll
        for (int nt = 0; nt < 8; ++nt) {
            int col = wn * 64 + nt * 8 + (lane & 3) * 2;
            *(float2*)&Y[row * HID + col]       = make_float2(accT[nt][0], accT[nt][1]);
            *(float2*)&Y[(row + 8) * HID + col] = make_float2(accT[nt][2], accT[nt][3]);
        }
    }
}

// ---------------- assign on HMMA: sims = E @ Pn^T, in-register argmax -------
__global__ void __launch_bounds__(256, 1) assign_mma_kernel(
    const float* __restrict__ E, const char* __restrict__ Pg,
    float* __restrict__ outA)
{
    extern __shared__ char smem[];
    const uint32_t Pbase = smem_u32(smem);
    const uint32_t Ebase = Pbase + EOFF;
    char* Eb = smem + EOFF;

    const int tid = threadIdx.x;
    const int wid = tid >> 5, lane = tid & 31;
    const int wm = wid >> 1, wn = wid & 1;
    const size_t row0 = (size_t)blockIdx.x * 128;

    for (int i = tid; i < (2 * PIMG) / 16; i += 256)
        cp16(Pbase + i * 16, Pg + i * 16);
    asm volatile("cp.async.commit_group;");

#pragma unroll
    for (int it = 0; it < 8; ++it) {
        int t = tid + it * 256;
        int r = t >> 4, blk = t & 15;
        const float4* xp = (const float4*)(E + (row0 + r) * HID + blk * 8);
        float4 x0 = xp[0], x1 = xp[1];
        float v[8] = {x0.x, x0.y, x0.z, x0.w, x1.x, x1.y, x1.z, x1.w};
        store8s(Eb, r * ESTR + blk * 16, EIMG, v);
    }
    asm volatile("cp.async.wait_group 0;");
    __syncthreads();

    const uint32_t aGeo = (wm * 32 + (lane & 15)) * ESTR + (lane >> 4) * 16;
    const uint32_t wRow = (uint32_t)(lane & 15) * PSTR;

    float best[2][2]; int bidx[2][2];
#pragma unroll
    for (int mt = 0; mt < 2; ++mt)
#pragma unroll
        for (int hf = 0; hf < 2; ++hf) { best[mt][hf] = -3.0e38f; bidx[mt][hf] = 0; }

#pragma unroll
    for (int pc = 0; pc < 2; ++pc) {
        const int pb = wn * 256 + pc * 128;
        float accP[2][8][4];
#pragma unroll
        for (int mt = 0; mt < 2; ++mt)
#pragma unroll
            for (int nt = 0; nt < 8; ++nt)
#pragma unroll
                for (int e = 0; e < 4; ++e) accP[mt][nt][e] = 0.0f;

#pragma unroll
        for (int half = 0; half < 2; ++half) {
            float accW[2][8][4];
#pragma unroll
            for (int mt = 0; mt < 2; ++mt)
#pragma unroll
                for (int nt = 0; nt < 8; ++nt)
#pragma unroll
                    for (int e = 0; e < 4; ++e) accW[mt][nt][e] = 0.0f;
#pragma unroll
            for (int ks2 = 0; ks2 < 4; ++ks2) {
                int ks = half * 4 + ks2;
                uint32_t ah[2][4], am[2][4];
#pragma unroll
                for (int mt = 0; mt < 2; ++mt) {
                    uint32_t a = Ebase + aGeo + mt * (16 * ESTR) + ks * 32;
                    ldm_x4(ah[mt], a);
                    ldm_x4(am[mt], a + EIMG);
                }
#pragma unroll
                for (int g = 0; g < 4; ++g) {
                    uint32_t wh[4], wmr[4];
                    uint32_t a = Pbase + wRow + ks * (16 * PSTR)
                               + pb + (lane >> 4) * 16 + g * 32;
                    ldm_x4t(wh,  a);
                    ldm_x4t(wmr, a + PIMG);
#pragma unroll
                    for (int mt = 0; mt < 2; ++mt) {
                        float* a0 = accW[mt][2 * g];
                        float* a1 = accW[mt][2 * g + 1];
                        mma16816(a0, ah[mt], wh);    mma16816(a1, ah[mt], wh + 2);
                        mma16816(a0, ah[mt], wmr);   mma16816(a1, ah[mt], wmr + 2);
                        mma16816(a0, am[mt], wh);    mma16816(a1, am[mt], wh + 2);
                    }
                }
            }
#pragma unroll
            for (int mt = 0; mt < 2; ++mt)
#pragma unroll
                for (int nt = 0; nt < 8; ++nt)
#pragma unroll
                    for (int e = 0; e < 4; ++e) accP[mt][nt][e] += accW[mt][nt][e];
        }

#pragma unroll
        for (int nt = 0; nt < 8; ++nt)
#pragma unroll
            for (int e = 0; e < 4; ++e) {
                int hf = e >> 1;
                int idx = wn * 128 + pc * 64 + nt * 8 + (lane & 3) * 2 + (e & 1);
#pragma unroll
                for (int mt = 0; mt < 2; ++mt)
                    if (accP[mt][nt][e] > best[mt][hf]) {
                        best[mt][hf] = accP[mt][nt][e];
                        bidx[mt][hf] = idx;
                    }
            }
    }

#pragma unroll
    for (int o = 1; o < 4; o <<= 1)
#pragma unroll
        for (int mt = 0; mt < 2; ++mt)
#pragma unroll
            for (int hf = 0; hf < 2; ++hf) {
                float ov = __shfl_xor_sync(0xffffffffu, best[mt][hf], o);
                int   oi = __shfl_xor_sync(0xffffffffu, bidx[mt][hf], o);
                if (ov > best[mt][hf] || (ov == best[mt][hf] && oi < bidx[mt][hf])) {
                    best[mt][hf] = ov; bidx[mt][hf] = oi;
                }
            }
    __syncthreads();
    float* sVal = (float*)smem;
    int*   sIdx = (int*)(smem + 2 * 128 * 4);
    if ((lane & 3) == 0) {
#pragma unroll
        for (int mt = 0; mt < 2; ++mt)
#pragma unroll
            for (int hf = 0; hf < 2; ++hf) {
                int r = wm * 32 + mt * 16 + (lane >> 2) + hf * 8;
                sVal[wn * 128 + r] = best[mt][hf];
                sIdx[wn * 128 + r] = bidx[mt][hf];
            }
    }
    __syncthreads();
    if (tid < 128) {
        float v0 = sVal[tid], v1 = sVal[128 + tid];
        int   i0 = sIdx[tid], i1 = sIdx[128 + tid];
        int bi = (v1 > v0 || (v1 == v0 && i1 < i0)) ? i1 : i0;
        outA[row0 + tid] = (float)bi;
    }
}

// ---------------- launch ----------------------------------------------------
extern "C" void kernel_launch(void* const* d_in, const int* in_sizes, int n_in,
                              void* d_out, int out_size)
{
    const float* x    = (const float*)d_in[0];
    const float* prot = (const float*)d_in[1];
    const float* grid = (const float*)d_in[2];
    const float* bw1  = (const float*)d_in[3];
    const float* sw1  = (const float*)d_in[4];
    const float* sc1  = (const float*)d_in[5];
    const float* bw2  = (const float*)d_in[6];
    const float* sw2  = (const float*)d_in[7];
    const float* sc2  = (const float*)d_in[8];
    float* out = (float*)d_out;

    const int N  = in_sizes[0] / HID;
    const int Kp = in_sizes[1] / HID;   // 256

    uint4 *W1, *W2, *ps; float *h;
    cudaGetSymbolAddress((void**)&W1, g_W1);
    cudaGetSymbolAddress((void**)&W2, g_W2);
    cudaGetSymbolAddress((void**)&h,  g_h);
    cudaGetSymbolAddress((void**)&ps, g_ps);

    cudaFuncSetAttribute(layer_mma_kernel,  cudaFuncAttributeMaxDynamicSharedMemorySize, SMEM_LAYER);
    cudaFuncSetAttribute(assign_mma_kernel, cudaFuncAttributeMaxDynamicSharedMemorySize, SMEM_ASSIGN);

    const int wtasks = NCH * 64 * HID;
    prep_w_kernel<<<(wtasks + 255) / 256, 256>>>(bw1, sw1, sc1, (char*)W1);
    prep_w_kernel<<<(wtasks + 255) / 256, 256>>>(bw2, sw2, sc2, (char*)W2);
    prep_p_kernel<<<Kp, HID>>>(prot, (char*)ps);

    layer_mma_kernel<<<N / BM, 256, SMEM_LAYER>>>(x, (const char*)W1, grid, h);
    layer_mma_kernel<<<N / BM, 256, SMEM_LAYER>>>(h, (const char*)W2, grid, out);

    if ((size_t)out_size >= (size_t)N * HID + (size_t)N)
        assign_mma_kernel<<<N / 128, 256, SMEM_ASSIGN>>>(out, (const char*)ps,
                                                         out + (size_t)N * HID);
}

// round 16
// speedup vs baseline: 2.8617x; 1.0142x over previous
#include <cuda_runtime.h>
#include <cuda_fp16.h>
#include <math.h>
#include <cstdint>

#define HID   128
#define NCH   18                 // 2 silu chunks + 16 spline chunks, 64 k each
#define BM    64                 // rows per CTA (half-size tile -> 2 CTAs/SM)
#define NMAX  131072
#define KPMAX 256

#define ASTR  144                // A row stride bytes (64 k * 2B + 16B pad)
#define ATILE (BM * ASTR)        // 9216 (one image)
#define ABUF  (2 * ATILE)        // 18432: hi | mid
#define WSTR  272                // W k-row stride bytes (128 o * 2B + 16B pad)
#define WIMG  17408              // 64 * 272 (one image)
#define WBLOB (2 * WIMG)         // 34816: hi | mid
#define WOFF  (2 * ABUF)         // 36864
#define SMEM_LAYER (WOFF + 2 * WBLOB)   // 106496 (x2 CTAs = 208KB <= 228KB/SM)

// assign kernel layout
#define PSTR  528                // proto k-row stride (256 protos * 2B + 16 pad)
#define PIMG  67584              // 128 * 528 (one image)
#define ESTR  272                // E row stride (128 k * 2B + 16 pad)
#define EIMG  34816              // 128 * 272
#define EOFF  (2 * PIMG)         // 135168
#define SMEM_ASSIGN (EOFF + 2 * EIMG)   // 204800

// ---------------- scratch (device globals; no allocation allowed) ----------
__device__ uint4 g_W1[(NCH * WBLOB) / 16];
__device__ uint4 g_W2[(NCH * WBLOB) / 16];
__device__ float g_h[(size_t)NMAX * HID];
__device__ uint4 g_ps[(2 * PIMG) / 16];   // pre-split normalized protos (hi|mid)

// ---------------- PTX helpers (sm_80-portable; no tcgen05) ------------------
__device__ __forceinline__ uint32_t smem_u32(const void* p) {
    uint32_t a;
    asm("{ .reg .u64 t; cvta.to.shared.u64 t, %1; cvt.u32.u64 %0, t; }" : "=r"(a) : "l"(p));
    return a;
}
__device__ __forceinline__ void ldm_x4(uint32_t* r, uint32_t a) {
    asm volatile("ldmatrix.sync.aligned.m8n8.x4.shared.b16 {%0,%1,%2,%3}, [%4];"
        : "=r"(r[0]), "=r"(r[1]), "=r"(r[2]), "=r"(r[3]) : "r"(a));
}
__device__ __forceinline__ void ldm_x4t(uint32_t* r, uint32_t a) {
    asm volatile("ldmatrix.sync.aligned.m8n8.x4.trans.shared.b16 {%0,%1,%2,%3}, [%4];"
        : "=r"(r[0]), "=r"(r[1]), "=r"(r[2]), "=r"(r[3]) : "r"(a));
}
// fp16 inputs, fp32 accumulator. fp16 split: h 11 bits, m next 11, eps~2^-22.
// Products hh+hm+mh suffice: the mm term is ~2^-24, BELOW the split floor.
__device__ __forceinline__ void mma16816(float* d, const uint32_t* a, const uint32_t* b) {
    asm volatile("mma.sync.aligned.m16n8k16.row.col.f32.f16.f16.f32 "
        "{%0,%1,%2,%3}, {%4,%5,%6,%7}, {%8,%9}, {%0,%1,%2,%3};"
        : "+f"(d[0]), "+f"(d[1]), "+f"(d[2]), "+f"(d[3])
        : "r"(a[0]), "r"(a[1]), "r"(a[2]), "r"(a[3]), "r"(b[0]), "r"(b[1]));
}
__device__ __forceinline__ void cp16(uint32_t saddr, const void* gaddr) {
    asm volatile("cp.async.cg.shared.global [%0], [%1], 16;" :: "r"(saddr), "l"(gaddr));
}

// ---------------- 2-way fp16 split (eps ~ 2^-22) ----------------------------
__device__ __forceinline__ void split2(float a, __half& h, __half& m) {
    h = __float2half_rn(a);
    m = __float2half_rn(a - __half2float(h));
}

// ---------------- weight prep: k-major fp16 hi/mid images -------------------
__global__ void prep_w_kernel(const float* __restrict__ bw,
                              const float* __restrict__ sw,
                              const float* __restrict__ sc,
                              char* __restrict__ Wout)
{
    int idx = blockIdx.x * 256 + threadIdx.x;      // (chunk, k, o)
    if (idx >= NCH * 64 * HID) return;
    int chunk = idx / (64 * HID);
    int rem   = idx - chunk * (64 * HID);
    int k = rem >> 7, o = rem & 127;
    float w;
    if (chunk < 2) {
        w = bw[o * HID + chunk * 64 + k];
    } else {
        int f = (chunk - 2) * 8 + (k >> 3);
        w = sw[(o * HID + f) * 8 + (k & 7)] * sc[o * HID + f];
    }
    __half h, m;
    split2(w, h, m);
    char* base = Wout + (size_t)chunk * WBLOB + k * WSTR + o * 2;
    *(__half*)(base)        = h;
    *(__half*)(base + WIMG) = m;
}

// ---------------- prototype prep: normalize + split to k-major images -------
__global__ void prep_p_kernel(const float* __restrict__ P, char* __restrict__ Pout)
{
    int r = blockIdx.x, t = threadIdx.x;           // r = proto, t = k
    float v = P[r * HID + t];
    float s = v * v;
#pragma unroll
    for (int o = 16; o > 0; o >>= 1) s += __shfl_xor_sync(0xffffffffu, s, o);
    __shared__ float red[4];
    if ((t & 31) == 0) red[t >> 5] = s;
    __syncthreads();
    float nrm = fmaxf(sqrtf(red[0] + red[1] + red[2] + red[3]), 1e-8f);
    __half h, m;
    split2(v / nrm, h, m);
    char* base = Pout + t * PSTR + r * 2;
    *(__half*)(base)        = h;
    *(__half*)(base + PIMG) = m;
}

// ---------------- A pack: 8 values -> fp16 hi/mid, 16B stores ---------------
__device__ __forceinline__ void store8s(char* Ab, uint32_t off, int img_stride,
                                        const float* v)
{
    __half h[8], m[8];
#pragma unroll
    for (int e = 0; e < 8; ++e) split2(v[e], h[e], m[e]);
    *(uint4*)(Ab + off)              = *(uint4*)h;
    *(uint4*)(Ab + img_stride + off) = *(uint4*)m;
}

// ---------------- A-chunk generation (reads x from gmem/L2) -----------------
__device__ __forceinline__ void gen_chunk(int cc, char* Ab, const float* __restrict__ X,
                                          size_t row0, int tid, float g0, float invh)
{
    if (cc < 2) {
#pragma unroll
        for (int it = 0; it < 2; ++it) {           // 64 rows x 8 blks = 512 tasks
            int t = tid + it * 256;
            int r = t >> 3, blk = t & 7;
            const float4* xp = (const float4*)(X + (row0 + r) * HID + cc * 64 + blk * 8);
            float4 x0 = xp[0], x1 = xp[1];
            float v[8] = {x0.x, x0.y, x0.z, x0.w, x1.x, x1.y, x1.z, x1.w};
#pragma unroll
            for (int e = 0; e < 8; ++e) {
                float x = v[e];
                v[e] = x / (1.0f + __expf(-x));
            }
            store8s(Ab, r * ASTR + blk * 16, ATILE, v);
        }
    } else {
        const int f0 = (cc - 2) * 8;
#pragma unroll
        for (int it = 0; it < 2; ++it) {           // 64 rows x 8 features
            int t = tid + it * 256;
            int r = t >> 3, fl = t & 7;
            float x = X[(row0 + r) * HID + f0 + fl];
            float tt = (x - g0) * invh;              // uniform-grid cubic B-spline
            float fi = floorf(tt);
            int   i  = (int)fi;
            float u  = tt - fi;
            float u2 = u * u, u3 = u2 * u, om = 1.0f - u;
            float c0v = u3 * (1.0f / 6.0f);
            float c1v = (1.0f / 6.0f) * (1.0f + 3.0f * u + 3.0f * u2 - 3.0f * u3);
            float c2v = (1.0f / 6.0f) * (4.0f - 6.0f * u2 + 3.0f * u3);
            float c3v = om * om * om * (1.0f / 6.0f);
            float v[8];
#pragma unroll
            for (int j = 0; j < 8; ++j) {
                int mm_ = i - j;
                float val = 0.0f;
                val = (mm_ == 0) ? c0v : val;
                val = (mm_ == 1) ? c1v : val;
                val = (mm_ == 2) ? c2v : val;
                val = (mm_ == 3) ? c3v : val;
                v[j] = val;
            }
            store8s(Ab, r * ASTR + fl * 16, ATILE, v);
        }
    }
}

// ---------------- fused KAN layer on HMMA (fp16x2, 3 products) --------------
// CTA: 64 rows x 128 outs, 8 warps in a 2x4 grid: wm=wid>>2 (32 rows),
// wn=wid&3 (32 cols). 32x32 warp tile: 8 ldmatrix per ks for 24 MMAs
// (was 10 per ks at 16x64) -> 20% less smem read traffic. 2 CTAs/SM.
__global__ void __launch_bounds__(256, 2) layer_mma_kernel(
    const float* __restrict__ X, const char* __restrict__ Wg,
    const float* __restrict__ grid, float* __restrict__ Y)
{
    extern __shared__ char smem[];
    const uint32_t Abase = smem_u32(smem);
    const uint32_t Wbase = Abase + WOFF;

    const int tid = threadIdx.x;
    const int wid = tid >> 5, lane = tid & 31;
    const int wm = wid >> 2, wn = wid & 3;
    const size_t row0 = (size_t)blockIdx.x * BM;

    const float g0   = grid[0];
    const float invh = 1.0f / (grid[1] - grid[0]);

    gen_chunk(0, smem, X, row0, tid, g0, invh);
    for (int i = tid; i < WBLOB / 16; i += 256)
        cp16(Wbase + i * 16, Wg + i * 16);
    asm volatile("cp.async.commit_group;");

    float accT[2][4][4];
#pragma unroll
    for (int mt = 0; mt < 2; ++mt)
#pragma unroll
        for (int nt = 0; nt < 4; ++nt)
#pragma unroll
            for (int e = 0; e < 4; ++e) accT[mt][nt][e] = 0.0f;

    const uint32_t aGeo = (wm * 32 + (lane & 15)) * ASTR + (lane >> 4) * 16;
    const uint32_t wCol = wn * 64 + (lane >> 4) * 16;      // 32 cols = 64 bytes
    const uint32_t wRow = (uint32_t)(lane & 15) * WSTR;

#pragma unroll 2
    for (int c = 0; c < NCH; ++c) {
        const int b = c & 1;

        if (c + 1 < NCH) {
            const char* src = Wg + (size_t)(c + 1) * WBLOB;
            uint32_t dst = Wbase + (b ^ 1) * WBLOB;
            for (int i = tid; i < WBLOB / 16; i += 256)
                cp16(dst + i * 16, src + i * 16);
            asm volatile("cp.async.commit_group;");
            asm volatile("cp.async.wait_group 1;");
        } else {
            asm volatile("cp.async.wait_group 0;");
        }
        __syncthreads();   // ALL threads' W(c) copies complete; A(c) visible

        float accW[2][4][4];
#pragma unroll
        for (int mt = 0; mt < 2; ++mt)
#pragma unroll
            for (int nt = 0; nt < 4; ++nt)
#pragma unroll
                for (int e = 0; e < 4; ++e) accW[mt][nt][e] = 0.0f;

        const uint32_t Ab_ = Abase + b * ABUF;
        const uint32_t Wb  = Wbase + b * WBLOB;
#pragma unroll
        for (int ks = 0; ks < 4; ++ks) {
            uint32_t ah[2][4], am[2][4];
#pragma unroll
            for (int mt = 0; mt < 2; ++mt) {
                uint32_t a = Ab_ + aGeo + mt * (16 * ASTR) + ks * 32;
                ldm_x4(ah[mt], a);
                ldm_x4(am[mt], a + ATILE);
            }
#pragma unroll
            for (int g = 0; g < 2; ++g) {
                uint32_t wh[4], wmr[4];
                uint32_t a = Wb + wRow + ks * (16 * WSTR) + wCol + g * 32;
                ldm_x4t(wh,  a);
                ldm_x4t(wmr, a + WIMG);
#pragma unroll
                for (int mt = 0; mt < 2; ++mt) {
                    float* a0 = accW[mt][2 * g];
                    float* a1 = accW[mt][2 * g + 1];
                    mma16816(a0, ah[mt], wh);       mma16816(a1, ah[mt], wh + 2);
                    mma16816(a0, ah[mt], wmr);      mma16816(a1, ah[mt], wmr + 2);
                    mma16816(a0, am[mt], wh);       mma16816(a1, am[mt], wh + 2);
                }
            }
        }

        if (c + 1 < NCH)
            gen_chunk(c + 1, smem + (b ^ 1) * ABUF, X, row0, tid, g0, invh);

#pragma unroll
        for (int mt = 0; mt < 2; ++mt)
#pragma unroll
            for (int nt = 0; nt < 4; ++nt)
#pragma unroll
                for (int e = 0; e < 4; ++e) accT[mt][nt][e] += accW[mt][nt][e];

        __syncthreads();
    }

    // epilogue: fragment -> gmem
#pragma unroll
    for (int mt = 0; mt < 2; ++mt) {
        size_t row = row0 + wm * 32 + mt * 16 + (lane >> 2);
#pragma unroll
        for (int nt = 0; nt < 4; ++nt) {
            int col = wn * 32 + nt * 8 + (lane & 3) * 2;
            *(float2*)&Y[row * HID + col]       = make_float2(accT[mt][nt][0], accT[mt][nt][1]);
            *(float2*)&Y[(row + 8) * HID + col] = make_float2(accT[mt][nt][2], accT[mt][nt][3]);
        }
    }
}

// ---------------- assign on HMMA: sims = E @ Pn^T, in-register argmax -------
__global__ void __launch_bounds__(256, 1) assign_mma_kernel(
    const float* __restrict__ E, const char* __restrict__ Pg,
    float* __restrict__ outA)
{
    extern __shared__ char smem[];
    const uint32_t Pbase = smem_u32(smem);
    const uint32_t Ebase = Pbase + EOFF;
    char* Eb = smem + EOFF;

    const int tid = threadIdx.x;
    const int wid = tid >> 5, lane = tid & 31;
    const int wm = wid >> 1, wn = wid & 1;
    const size_t row0 = (size_t)blockIdx.x * 128;

    for (int i = tid; i < (2 * PIMG) / 16; i += 256)
        cp16(Pbase + i * 16, Pg + i * 16);
    asm volatile("cp.async.commit_group;");

#pragma unroll
    for (int it = 0; it < 8; ++it) {
        int t = tid + it * 256;
        int r = t >> 4, blk = t & 15;
        const float4* xp = (const float4*)(E + (row0 + r) * HID + blk * 8);
        float4 x0 = xp[0], x1 = xp[1];
        float v[8] = {x0.x, x0.y, x0.z, x0.w, x1.x, x1.y, x1.z, x1.w};
        store8s(Eb, r * ESTR + blk * 16, EIMG, v);
    }
    asm volatile("cp.async.wait_group 0;");
    __syncthreads();

    const uint32_t aGeo = (wm * 32 + (lane & 15)) * ESTR + (lane >> 4) * 16;
    const uint32_t wRow = (uint32_t)(lane & 15) * PSTR;

    float best[2][2]; int bidx[2][2];
#pragma unroll
    for (int mt = 0; mt < 2; ++mt)
#pragma unroll
        for (int hf = 0; hf < 2; ++hf) { best[mt][hf] = -3.0e38f; bidx[mt][hf] = 0; }

#pragma unroll
    for (int pc = 0; pc < 2; ++pc) {
        const int pb = wn * 256 + pc * 128;
        float accP[2][8][4];
#pragma unroll
        for (int mt = 0; mt < 2; ++mt)
#pragma unroll
            for (int nt = 0; nt < 8; ++nt)
#pragma unroll
                for (int e = 0; e < 4; ++e) accP[mt][nt][e] = 0.0f;

#pragma unroll
        for (int half = 0; half < 2; ++half) {
            float accW[2][8][4];
#pragma unroll
            for (int mt = 0; mt < 2; ++mt)
#pragma unroll
                for (int nt = 0; nt < 8; ++nt)
#pragma unroll
                    for (int e = 0; e < 4; ++e) accW[mt][nt][e] = 0.0f;
#pragma unroll
            for (int ks2 = 0; ks2 < 4; ++ks2) {
                int ks = half * 4 + ks2;
                uint32_t ah[2][4], am[2][4];
#pragma unroll
                for (int mt = 0; mt < 2; ++mt) {
                    uint32_t a = Ebase + aGeo + mt * (16 * ESTR) + ks * 32;
                    ldm_x4(ah[mt], a);
                    ldm_x4(am[mt], a + EIMG);
                }
#pragma unroll
                for (int g = 0; g < 4; ++g) {
                    uint32_t wh[4], wmr[4];
                    uint32_t a = Pbase + wRow + ks * (16 * PSTR)
                               + pb + (lane >> 4) * 16 + g * 32;
                    ldm_x4t(wh,  a);
                    ldm_x4t(wmr, a + PIMG);
#pragma unroll
                    for (int mt = 0; mt < 2; ++mt) {
                        float* a0 = accW[mt][2 * g];
                        float* a1 = accW[mt][2 * g + 1];
                        mma16816(a0, ah[mt], wh);    mma16816(a1, ah[mt], wh + 2);
                        mma16816(a0, ah[mt], wmr);   mma16816(a1, ah[mt], wmr + 2);
                        mma16816(a0, am[mt], wh);    mma16816(a1, am[mt], wh + 2);
                    }
                }
            }
#pragma unroll
            for (int mt = 0; mt < 2; ++mt)
#pragma unroll
                for (int nt = 0; nt < 8; ++nt)
#pragma unroll
                    for (int e = 0; e < 4; ++e) accP[mt][nt][e] += accW[mt][nt][e];
        }

#pragma unroll
        for (int nt = 0; nt < 8; ++nt)
#pragma unroll
            for (int e = 0; e < 4; ++e) {
                int hf = e >> 1;
                int idx = wn * 128 + pc * 64 + nt * 8 + (lane & 3) * 2 + (e & 1);
#pragma unroll
                for (int mt = 0; mt < 2; ++mt)
                    if (accP[mt][nt][e] > best[mt][hf]) {
                        best[mt][hf] = accP[mt][nt][e];
                        bidx[mt][hf] = idx;
                    }
            }
    }

#pragma unroll
    for (int o = 1; o < 4; o <<= 1)
#pragma unroll
        for (int mt = 0; mt < 2; ++mt)
#pragma unroll
            for (int hf = 0; hf < 2; ++hf) {
                float ov = __shfl_xor_sync(0xffffffffu, best[mt][hf], o);
                int   oi = __shfl_xor_sync(0xffffffffu, bidx[mt][hf], o);
                if (ov > best[mt][hf] || (ov == best[mt][hf] && oi < bidx[mt][hf])) {
                    best[mt][hf] = ov; bidx[mt][hf] = oi;
                }
            }
    __syncthreads();
    float* sVal = (float*)smem;
    int*   sIdx = (int*)(smem + 2 * 128 * 4);
    if ((lane & 3) == 0) {
#pragma unroll
        for (int mt = 0; mt < 2; ++mt)
#pragma unroll
            for (int hf = 0; hf < 2; ++hf) {
                int r = wm * 32 + mt * 16 + (lane >> 2) + hf * 8;
                sVal[wn * 128 + r] = best[mt][hf];
                sIdx[wn * 128 + r] = bidx[mt][hf];
            }
    }
    __syncthreads();
    if (tid < 128) {
        float v0 = sVal[tid], v1 = sVal[128 + tid];
        int   i0 = sIdx[tid], i1 = sIdx[128 + tid];
        int bi = (v1 > v0 || (v1 == v0 && i1 < i0)) ? i1 : i0;
        outA[row0 + tid] = (float)bi;
    }
}

// ---------------- launch ----------------------------------------------------
extern "C" void kernel_launch(void* const* d_in, const int* in_sizes, int n_in,
                              void* d_out, int out_size)
{
    const float* x    = (const float*)d_in[0];
    const float* prot = (const float*)d_in[1];
    const float* grid = (const float*)d_in[2];
    const float* bw1  = (const float*)d_in[3];
    const float* sw1  = (const float*)d_in[4];
    const float* sc1  = (const float*)d_in[5];
    const float* bw2  = (const float*)d_in[6];
    const float* sw2  = (const float*)d_in[7];
    const float* sc2  = (const float*)d_in[8];
    float* out = (float*)d_out;

    const int N  = in_sizes[0] / HID;
    const int Kp = in_sizes[1] / HID;   // 256

    uint4 *W1, *W2, *ps; float *h;
    cudaGetSymbolAddress((void**)&W1, g_W1);
    cudaGetSymbolAddress((void**)&W2, g_W2);
    cudaGetSymbolAddress((void**)&h,  g_h);
    cudaGetSymbolAddress((void**)&ps, g_ps);

    cudaFuncSetAttribute(layer_mma_kernel,  cudaFuncAttributeMaxDynamicSharedMemorySize, SMEM_LAYER);
    cudaFuncSetAttribute(assign_mma_kernel, cudaFuncAttributeMaxDynamicSharedMemorySize, SMEM_ASSIGN);

    const int wtasks = NCH * 64 * HID;
    prep_w_kernel<<<(wtasks + 255) / 256, 256>>>(bw1, sw1, sc1, (char*)W1);
    prep_w_kernel<<<(wtasks + 255) / 256, 256>>>(bw2, sw2, sc2, (char*)W2);
    prep_p_kernel<<<Kp, HID>>>(prot, (char*)ps);

    layer_mma_kernel<<<N / BM, 256, SMEM_LAYER>>>(x, (const char*)W1, grid, h);
    layer_mma_kernel<<<N / BM, 256, SMEM_LAYER>>>(h, (const char*)W2, grid, out);

    if ((size_t)out_size >= (size_t)N * HID + (size_t)N)
        assign_mma_kernel<<<N / 128, 256, SMEM_ASSIGN>>>(out, (const char*)ps,
                                                         out + (size_t)N * HID);
}